// round 11
// baseline (speedup 1.0000x reference)
#include <cuda_runtime.h>
#include <cuda_bf16.h>
#include <cstdint>

#define BS 8
#define SEQ 512
#define DM 512
#define NROW (BS*SEQ)          // 4096
#define KEXT 3072              // 6 segments x 512

// ---------------- scratch (no allocation allowed) ----------------
__device__ __align__(16) float g_qkv[NROW * 1024];    // [Q(256)|K(256)|V(512)] self
__device__ __align__(16) float g_kvenc[NROW * 768];   // [K(256)|V(512)] encoder
__device__ __align__(16) float g_q2a[NROW * 256];     // cross-Q split-K partial 0
__device__ __align__(16) float g_q2b[NROW * 256];     // cross-Q split-K partial 1
__device__ __align__(16) float g_fx2[NROW * 512];     // cross-attn output
__device__ __align__(16) __nv_bfloat16 g_xs [NROW * KEXT];   // x   split-extended
__device__ __align__(16) __nv_bfloat16 g_xes[NROW * KEXT];   // xe  split-extended
__device__ __align__(16) __nv_bfloat16 g_fxs[NROW * KEXT];   // fx  split-extended
__device__ __align__(16) __nv_bfloat16 g_ball[1792 * KEXT];  // [Wq|Wk|Wv|Wk|Wv]^T split

// ---------------- helpers ----------------
__device__ __forceinline__ uint32_t smem_u32(const void* p) {
    uint32_t a;
    asm("{ .reg .u64 t; cvta.to.shared.u64 t, %1; cvt.u32.u64 %0, t; }" : "=r"(a) : "l"(p));
    return a;
}
__device__ __forceinline__ float ex2(float x) {
    float y; asm("ex2.approx.f32 %0, %1;" : "=f"(y) : "f"(x)); return y;
}
__device__ __forceinline__ unsigned long long pk2(float x, float y) {
    unsigned long long r; asm("mov.b64 %0, {%1,%2};" : "=l"(r) : "f"(x), "f"(y)); return r;
}
__device__ __forceinline__ void fma2(unsigned long long& d, unsigned long long a, unsigned long long b) {
    asm("fma.rn.f32x2 %0, %1, %2, %0;" : "+l"(d) : "l"(a), "l"(b));
}
__device__ __forceinline__ float2 up2(unsigned long long v) {
    float2 r; asm("mov.b64 {%0,%1}, %2;" : "=f"(r.x), "=f"(r.y) : "l"(v)); return r;
}
__device__ __forceinline__ void cpasync16(uint32_t dst, const void* src) {
    asm volatile("cp.async.cg.shared.global [%0], [%1], 16;" :: "r"(dst), "l"(src));
}

__device__ __forceinline__ void split3(float v, __nv_bfloat16& h, __nv_bfloat16& m, __nv_bfloat16& l) {
    h = __float2bfloat16(v);
    float r1 = v - __bfloat162float(h);
    m = __float2bfloat16(r1);
    float r2 = r1 - __bfloat162float(m);
    l = __float2bfloat16(r2);
}

// ---------------- split kernels ----------------
// A segments: [hi, hi, mid, hi, lo, mid]; handles x and xe in one launch.
__global__ __launch_bounds__(256) void splitAB_k(const float* __restrict__ x, const float* __restrict__ xe,
                                                 __nv_bfloat16* __restrict__ xs, __nv_bfloat16* __restrict__ xes)
{
    int gid = blockIdx.x * 256 + threadIdx.x;   // 2 * NROW*512
    const float* in; __nv_bfloat16* out; int id;
    if (gid < NROW * 512) { in = x; out = xs; id = gid; }
    else { in = xe; out = xes; id = gid - NROW * 512; }
    int r = id >> 9, c = id & 511;
    __nv_bfloat16 h, m, l;
    split3(in[id], h, m, l);
    __nv_bfloat16* o = out + (size_t)r * KEXT + c;
    o[0] = h; o[512] = h; o[1024] = m; o[1536] = h; o[2048] = l; o[2560] = m;
}

// B rows: g_ball[n][k] = W[k][n], segments [hi, mid, hi, lo, hi, mid]
__global__ void splitW_k(const float* __restrict__ Wq, const float* __restrict__ Wk,
                         const float* __restrict__ Wv, __nv_bfloat16* __restrict__ out)
{
    __shared__ float s[32][33];
    const int k0 = blockIdx.x * 32, n0 = blockIdx.y * 32;
    const int tx = threadIdx.x, ty = threadIdx.y;   // 32 x 8

    const float* src; int col0, ldw;
    if      (n0 < 256)  { src = Wq; col0 = n0;        ldw = 256; }
    else if (n0 < 512)  { src = Wk; col0 = n0 - 256;  ldw = 256; }
    else if (n0 < 1024) { src = Wv; col0 = n0 - 512;  ldw = 512; }
    else if (n0 < 1280) { src = Wk; col0 = n0 - 1024; ldw = 256; }
    else                { src = Wv; col0 = n0 - 1280; ldw = 512; }

#pragma unroll
    for (int i = 0; i < 4; i++) {
        int kk = ty + i * 8;
        s[kk][tx] = src[(k0 + kk) * ldw + col0 + tx];
    }
    __syncthreads();
#pragma unroll
    for (int i = 0; i < 4; i++) {
        int nn = ty + i * 8;
        __nv_bfloat16 h, m, l;
        split3(s[tx][nn], h, m, l);
        __nv_bfloat16* o = out + (size_t)(n0 + nn) * KEXT + k0 + tx;
        o[0] = h; o[512] = m; o[1024] = h; o[1536] = l; o[2048] = h; o[2560] = m;
    }
}

// ---------------- mma.sync GEMM body: 128x128 CTA tile, KC=32 (best-measured) ----------------
struct SmemMM {
    __nv_bfloat16 sA[2][128][40];   // 40 = 32 + pad (conflict-free)
    __nv_bfloat16 sB[2][128][40];
};

__device__ __forceinline__ void mma_body(SmemMM& sm,
    const __nv_bfloat16* __restrict__ A, const __nv_bfloat16* __restrict__ B,
    float* __restrict__ C, int ldc, int nch)
{
    const int tid = threadIdx.x;
    const int wid = tid >> 5, lane = tid & 31;

    const uint32_t sAb = smem_u32(&sm.sA[0][0][0]);
    const uint32_t sBb = smem_u32(&sm.sB[0][0][0]);
    const uint32_t STAGE = 128 * 80;

    auto issue = [&](int c, int buf) {
#pragma unroll
        for (int i = 0; i < 2; i++) {
            int g = tid + i * 256;
            int r = g >> 2, j = g & 3;
            uint32_t so = (uint32_t)buf * STAGE + r * 80 + j * 16;
            cpasync16(sAb + so, (const char*)(A + (size_t)r * KEXT + c * 32 + j * 8));
            cpasync16(sBb + so, (const char*)(B + (size_t)r * KEXT + c * 32 + j * 8));
        }
    };

    issue(0, 0);
    asm volatile("cp.async.commit_group;" ::: "memory");
    issue(1, 1);
    asm volatile("cp.async.commit_group;" ::: "memory");

    float acc[4][4][4];
#pragma unroll
    for (int i = 0; i < 4; i++)
#pragma unroll
        for (int j = 0; j < 4; j++)
#pragma unroll
            for (int k = 0; k < 4; k++) acc[i][j][k] = 0.f;

    const int wm = wid >> 2, wn = wid & 3;
    const int rbase = wm * 64 + (lane >> 2);
    const int nbase = wn * 32 + (lane >> 2);
    const int lq = lane & 3;

    for (int c = 0; c < nch; c++) {
        asm volatile("cp.async.wait_group 1;" ::: "memory");
        __syncthreads();
        const uint32_t* sA32 = (const uint32_t*)&sm.sA[c & 1][0][0];
        const uint32_t* sB32 = (const uint32_t*)&sm.sB[c & 1][0][0];

#pragma unroll
        for (int ks = 0; ks < 2; ks++) {
            const int cw = ks * 8 + lq;
            uint32_t af[4][4], bf[4][2];
#pragma unroll
            for (int am = 0; am < 4; am++) {
                int r = rbase + am * 16;
                af[am][0] = sA32[r * 20 + cw];
                af[am][1] = sA32[(r + 8) * 20 + cw];
                af[am][2] = sA32[r * 20 + cw + 4];
                af[am][3] = sA32[(r + 8) * 20 + cw + 4];
            }
#pragma unroll
            for (int an = 0; an < 4; an++) {
                int n = nbase + an * 8;
                bf[an][0] = sB32[n * 20 + cw];
                bf[an][1] = sB32[n * 20 + cw + 4];
            }
#pragma unroll
            for (int am = 0; am < 4; am++)
#pragma unroll
                for (int an = 0; an < 4; an++) {
                    asm volatile(
                        "mma.sync.aligned.m16n8k16.row.col.f32.bf16.bf16.f32 "
                        "{%0,%1,%2,%3}, {%4,%5,%6,%7}, {%8,%9}, {%0,%1,%2,%3};"
                        : "+f"(acc[am][an][0]), "+f"(acc[am][an][1]),
                          "+f"(acc[am][an][2]), "+f"(acc[am][an][3])
                        : "r"(af[am][0]), "r"(af[am][1]), "r"(af[am][2]), "r"(af[am][3]),
                          "r"(bf[an][0]), "r"(bf[an][1]));
                }
        }
        __syncthreads();
        if (c + 2 < nch) issue(c + 2, c & 1);
        asm volatile("cp.async.commit_group;" ::: "memory");
    }

#pragma unroll
    for (int am = 0; am < 4; am++) {
#pragma unroll
        for (int an = 0; an < 4; an++) {
            int r0 = wm * 64 + am * 16 + (lane >> 2);
            int cc = wn * 32 + an * 8 + lq * 2;
            *(float2*)&C[r0 * ldc + cc]       = make_float2(acc[am][an][0], acc[am][an][1]);
            *(float2*)&C[(r0 + 8) * ldc + cc] = make_float2(acc[am][an][2], acc[am][an][3]);
        }
    }
}

// fused projections, 448 blocks, heavy (6-limb) first, light (3-limb enc-V) last
__global__ __launch_bounds__(256, 2) void proj_k(
    const __nv_bfloat16* __restrict__ xs, const __nv_bfloat16* __restrict__ xes,
    const __nv_bfloat16* __restrict__ ball, float* __restrict__ qkv, float* __restrict__ kvenc)
{
    __shared__ SmemMM sm;
    const int bid = blockIdx.x;
    const __nv_bfloat16 *A, *B; float* C; int ldc, nch, bx, by;
    if (bid < 256) {
        bx = bid & 7; by = bid >> 3;
        A = xs; B = ball; C = qkv; ldc = 1024; nch = 96;
    } else if (bid < 320) {
        int i = bid - 256; bx = i & 1; by = i >> 1;
        A = xes; B = ball + (size_t)1024 * KEXT; C = kvenc; ldc = 768; nch = 96;
    } else {
        int i = bid - 320; bx = 2 + (i & 3); by = i >> 2;
        A = xes; B = ball + (size_t)1024 * KEXT; C = kvenc; ldc = 768; nch = 48;
    }
    mma_body(sm, A + (size_t)by * 128 * KEXT, B + (size_t)bx * 128 * KEXT,
             C + (size_t)by * 128 * ldc + bx * 128, ldc, nch);
}

// cross-Q GEMM: split-K=2 over the 6 segments: half0 = [h,h,m], half1 = [h,l,m]
__global__ __launch_bounds__(256, 2) void crossq_k(
    const __nv_bfloat16* __restrict__ fxs, const __nv_bfloat16* __restrict__ ball,
    float* __restrict__ q2a, float* __restrict__ q2b)
{
    __shared__ SmemMM sm;
    const int bid = blockIdx.x;            // 128
    const int half = bid >> 6;
    const int i = bid & 63;
    const int bx = i & 1, by = i >> 1;
    const __nv_bfloat16* A = fxs + half * 1536;
    const __nv_bfloat16* B = ball + half * 1536;
    float* C = half ? q2b : q2a;
    mma_body(sm, A + (size_t)by * 128 * KEXT, B + (size_t)bx * 128 * KEXT,
             C + (size_t)by * 128 * 256 + bx * 128, 256, 48);
}

// ---------------- Attention (1 query/thread, 2-pass, FFMA2, base-2 softmax) ----------------
// Best-measured attention (106 us causal). Causal quirk: masked zeros participate
// in softmax; masked V tail via warp-scan suffix sums.
template <int CAUSAL, int QSUM, int WSPLIT>
__global__ __launch_bounds__(512, 2) void attn2_k(
    const float* __restrict__ Qbuf, const float* __restrict__ Qbuf2, int ldq, int qoff,
    const float* __restrict__ KVbuf, int ldkv, int koff, int voff,
    float* __restrict__ Out, __nv_bfloat16* __restrict__ OutS)
{
    __shared__ float sKt[4][512];                 // K transposed: [dim][key]
    __shared__ __align__(16) float sV[512 * 8];   // V row-major:  [key][dim]
    __shared__ float sWS[16][8];                  // warp V-sums for suffix scan

    const int bh = blockIdx.x;
    const int h = bh & 63, b = bh >> 6;
    const int t = threadIdx.x, lane = t & 31, wid = t >> 5;
    const int rowbase = b * SEQ + t;

    const float* kv = KVbuf + (size_t)rowbase * ldkv;
    float4 kk = *(const float4*)(kv + koff + h * 4);
    sKt[0][t] = kk.x; sKt[1][t] = kk.y; sKt[2][t] = kk.z; sKt[3][t] = kk.w;
    float4 v0 = *(const float4*)(kv + voff + h * 8);
    float4 v1 = *(const float4*)(kv + voff + h * 8 + 4);
    *(float4*)&sV[t * 8] = v0;
    *(float4*)&sV[t * 8 + 4] = v1;

    float suf[8];
    if (CAUSAL) {
        float vown[8] = {v0.x, v0.y, v0.z, v0.w, v1.x, v1.y, v1.z, v1.w};
#pragma unroll
        for (int d = 0; d < 8; d++) suf[d] = vown[d];
#pragma unroll
        for (int off = 1; off < 32; off <<= 1) {
#pragma unroll
            for (int d = 0; d < 8; d++) {
                float o = __shfl_down_sync(0xffffffffu, suf[d], off);
                if (lane + off < 32) suf[d] += o;
            }
        }
        if (lane == 0) {
#pragma unroll
            for (int d = 0; d < 8; d++) sWS[wid][d] = suf[d];
        }
        __syncthreads();
        for (int w = wid + 1; w < 16; w++)
#pragma unroll
            for (int d = 0; d < 8; d++) suf[d] += sWS[w][d];
#pragma unroll
        for (int d = 0; d < 8; d++) suf[d] -= vown[d];   // sum_{k > t}
    } else {
        __syncthreads();
    }

    const int q = t;
    const float SCQ = 0.72134752044448170f;  // 0.5 * log2(e)
    float4 qv = *(const float4*)(Qbuf + (size_t)rowbase * ldq + qoff + h * 4);
    if (QSUM) {
        float4 q2v = *(const float4*)(Qbuf2 + (size_t)rowbase * ldq + qoff + h * 4);
        qv.x += q2v.x; qv.y += q2v.y; qv.z += q2v.z; qv.w += q2v.w;
    }
    const float qs0 = qv.x * SCQ, qs1 = qv.y * SCQ, qs2 = qv.z * SCQ, qs3 = qv.w * SCQ;
    unsigned long long aq0 = pk2(qs0, qs0), aq1 = pk2(qs1, qs1);
    unsigned long long aq2 = pk2(qs2, qs2), aq3 = pk2(qs3, qs3);

    const int n = CAUSAL ? (q + 1) : SEQ;
    const int nquad = n >> 2;

    float m = CAUSAL ? 0.f : -3.0e38f;
    for (int i = 0; i < nquad; i++) {
        const int k4 = i << 2;
        ulonglong2 k0 = *(const ulonglong2*)&sKt[0][k4];
        ulonglong2 k1 = *(const ulonglong2*)&sKt[1][k4];
        ulonglong2 k2 = *(const ulonglong2*)&sKt[2][k4];
        ulonglong2 k3 = *(const ulonglong2*)&sKt[3][k4];
        unsigned long long s01 = 0ULL, s23 = 0ULL;
        fma2(s01, aq0, k0.x); fma2(s23, aq0, k0.y);
        fma2(s01, aq1, k1.x); fma2(s23, aq1, k1.y);
        fma2(s01, aq2, k2.x); fma2(s23, aq2, k2.y);
        fma2(s01, aq3, k3.x); fma2(s23, aq3, k3.y);
        float2 f01 = up2(s01), f23 = up2(s23);
        m = fmaxf(m, fmaxf(fmaxf(f01.x, f01.y), fmaxf(f23.x, f23.y)));
    }
    for (int k = nquad << 2; k < n; k++) {
        float s = fmaf(qs0, sKt[0][k], fmaf(qs1, sKt[1][k], fmaf(qs2, sKt[2][k], qs3 * sKt[3][k])));
        m = fmaxf(m, s);
    }

    const unsigned long long nm = pk2(-m, -m);
    float denom = 0.f;
    unsigned long long acc0 = 0, acc1 = 0, acc2 = 0, acc3 = 0;
    for (int i = 0; i < nquad; i++) {
        const int k4 = i << 2;
        ulonglong2 k0 = *(const ulonglong2*)&sKt[0][k4];
        ulonglong2 k1 = *(const ulonglong2*)&sKt[1][k4];
        ulonglong2 k2 = *(const ulonglong2*)&sKt[2][k4];
        ulonglong2 k3 = *(const ulonglong2*)&sKt[3][k4];
        unsigned long long s01 = nm, s23 = nm;
        fma2(s01, aq0, k0.x); fma2(s23, aq0, k0.y);
        fma2(s01, aq1, k1.x); fma2(s23, aq1, k1.y);
        fma2(s01, aq2, k2.x); fma2(s23, aq2, k2.y);
        fma2(s01, aq3, k3.x); fma2(s23, aq3, k3.y);
        float2 f01 = up2(s01), f23 = up2(s23);
        float p0 = ex2(f01.x), p1 = ex2(f01.y), p2 = ex2(f23.x), p3 = ex2(f23.y);
        denom += (p0 + p1) + (p2 + p3);
        const float* vb = &sV[k4 * 8];
        {
            unsigned long long P = pk2(p0, p0);
            ulonglong2 va = *(const ulonglong2*)(vb);
            ulonglong2 vc = *(const ulonglong2*)(vb + 4);
            fma2(acc0, P, va.x); fma2(acc1, P, va.y); fma2(acc2, P, vc.x); fma2(acc3, P, vc.y);
        }
        {
            unsigned long long P = pk2(p1, p1);
            ulonglong2 va = *(const ulonglong2*)(vb + 8);
            ulonglong2 vc = *(const ulonglong2*)(vb + 12);
            fma2(acc0, P, va.x); fma2(acc1, P, va.y); fma2(acc2, P, vc.x); fma2(acc3, P, vc.y);
        }
        {
            unsigned long long P = pk2(p2, p2);
            ulonglong2 va = *(const ulonglong2*)(vb + 16);
            ulonglong2 vc = *(const ulonglong2*)(vb + 20);
            fma2(acc0, P, va.x); fma2(acc1, P, va.y); fma2(acc2, P, vc.x); fma2(acc3, P, vc.y);
        }
        {
            unsigned long long P = pk2(p3, p3);
            ulonglong2 va = *(const ulonglong2*)(vb + 24);
            ulonglong2 vc = *(const ulonglong2*)(vb + 28);
            fma2(acc0, P, va.x); fma2(acc1, P, va.y); fma2(acc2, P, vc.x); fma2(acc3, P, vc.y);
        }
    }
    for (int k = nquad << 2; k < n; k++) {
        float s = -m + fmaf(qs0, sKt[0][k], fmaf(qs1, sKt[1][k], fmaf(qs2, sKt[2][k], qs3 * sKt[3][k])));
        float p = ex2(s);
        denom += p;
        unsigned long long P = pk2(p, p);
        const float* vb = &sV[k * 8];
        ulonglong2 va = *(const ulonglong2*)(vb);
        ulonglong2 vc = *(const ulonglong2*)(vb + 4);
        fma2(acc0, P, va.x); fma2(acc1, P, va.y); fma2(acc2, P, vc.x); fma2(acc3, P, vc.y);
    }

    if (CAUSAL) {
        float pm = ex2(-m);
        denom += (float)(SEQ - 1 - q) * pm;
        unsigned long long P = pk2(pm, pm);
        fma2(acc0, P, pk2(suf[0], suf[1]));
        fma2(acc1, P, pk2(suf[2], suf[3]));
        fma2(acc2, P, pk2(suf[4], suf[5]));
        fma2(acc3, P, pk2(suf[6], suf[7]));
    }

    const float inv = 1.0f / denom;
    float2 o0 = up2(acc0), o1 = up2(acc1), o2 = up2(acc2), o3 = up2(acc3);
    float vals[8] = {o0.x * inv, o0.y * inv, o1.x * inv, o1.y * inv,
                     o2.x * inv, o2.y * inv, o3.x * inv, o3.y * inv};

    if (WSPLIT) {
        __align__(16) __nv_bfloat16 H[8], M[8], L[8];
#pragma unroll
        for (int d = 0; d < 8; d++) split3(vals[d], H[d], M[d], L[d]);
        __nv_bfloat16* ob = OutS + (size_t)rowbase * KEXT + h * 8;
        *(uint4*)(ob)        = *(uint4*)H;
        *(uint4*)(ob + 512)  = *(uint4*)H;
        *(uint4*)(ob + 1024) = *(uint4*)M;
        *(uint4*)(ob + 1536) = *(uint4*)H;
        *(uint4*)(ob + 2048) = *(uint4*)L;
        *(uint4*)(ob + 2560) = *(uint4*)M;
    } else {
        float* o = Out + (size_t)rowbase * DM + h * 8;
        *(float4*)(o)     = make_float4(vals[0], vals[1], vals[2], vals[3]);
        *(float4*)(o + 4) = make_float4(vals[4], vals[5], vals[6], vals[7]);
    }
}

// ---------------- Residual + LayerNorm + FFN (hidden=10) fused ----------------
#define HIDD 10
__global__ __launch_bounds__(256) void lnffn_k(
    const float* __restrict__ x, const float* __restrict__ fx,
    const float* __restrict__ lg, const float* __restrict__ lb,
    const float* __restrict__ w1, const float* __restrict__ b1,
    const float* __restrict__ w2, const float* __restrict__ b2,
    float* __restrict__ out)
{
    const int row = blockIdx.x;
    const int t = threadIdx.x;
    const int warp = t >> 5, lane = t & 31;

    const float* xr = x + row * DM;
    const float* fr = fx + row * DM;
    float v0 = xr[t] + fr[t];
    float v1 = xr[t + 256] + fr[t + 256];

    float s = v0 + v1;
    float ss = v0 * v0 + v1 * v1;
#pragma unroll
    for (int o = 16; o > 0; o >>= 1) {
        s  += __shfl_down_sync(0xffffffffu, s,  o);
        ss += __shfl_down_sync(0xffffffffu, ss, o);
    }
    __shared__ float rs[8], rss[8];
    if (lane == 0) { rs[warp] = s; rss[warp] = ss; }
    __syncthreads();
    float S = 0.f, SS = 0.f;
#pragma unroll
    for (int w = 0; w < 8; w++) { S += rs[w]; SS += rss[w]; }
    const float mu = S * (1.0f / DM);
    const float var = SS * (1.0f / DM) - mu * mu;
    const float rstd = rsqrtf(var + 1e-5f);

    const float y0 = (v0 - mu) * rstd * lg[t] + lb[t];
    const float y1 = (v1 - mu) * rstd * lg[t + 256] + lb[t + 256];

    float pj[HIDD];
#pragma unroll
    for (int j = 0; j < HIDD; j++)
        pj[j] = y0 * __ldg(&w1[j * DM + t]) + y1 * __ldg(&w1[j * DM + t + 256]);
#pragma unroll
    for (int j = 0; j < HIDD; j++)
#pragma unroll
        for (int o = 16; o > 0; o >>= 1)
            pj[j] += __shfl_down_sync(0xffffffffu, pj[j], o);

    __shared__ float hred[8][HIDD];
    if (lane == 0)
#pragma unroll
        for (int j = 0; j < HIDD; j++) hred[warp][j] = pj[j];
    __syncthreads();

    __shared__ float sh[HIDD];
    if (t < HIDD) {
        float hv = b1[t];
#pragma unroll
        for (int w = 0; w < 8; w++) hv += hred[w][t];
        sh[t] = fmaxf(hv, 0.f);
    }
    __syncthreads();

    float o0 = b2[t], o1 = b2[t + 256];
#pragma unroll
    for (int j = 0; j < HIDD; j++) {
        const float hj = sh[j];
        o0 = fmaf(hj, __ldg(&w2[t * HIDD + j]), o0);
        o1 = fmaf(hj, __ldg(&w2[(t + 256) * HIDD + j]), o1);
    }
    out[row * DM + t] = o0;
    out[row * DM + t + 256] = o1;
}

// ---------------- launch ----------------
extern "C" void kernel_launch(void* const* d_in, const int* in_sizes, int n_in,
                              void* d_out, int out_size)
{
    const float* x   = (const float*)d_in[0];
    const float* xe  = (const float*)d_in[1];
    const float* Wq  = (const float*)d_in[2];
    const float* Wk  = (const float*)d_in[3];
    const float* Wv  = (const float*)d_in[4];
    const float* lg  = (const float*)d_in[5];
    const float* lb  = (const float*)d_in[6];
    const float* w1  = (const float*)d_in[7];
    const float* b1  = (const float*)d_in[8];
    const float* w2  = (const float*)d_in[9];
    const float* b2  = (const float*)d_in[10];
    float* out = (float*)d_out;

    float *qkv, *kvenc, *q2a, *q2b, *fx2;
    __nv_bfloat16 *xs, *xes, *fxs, *ball;
    cudaGetSymbolAddress((void**)&qkv,   g_qkv);
    cudaGetSymbolAddress((void**)&kvenc, g_kvenc);
    cudaGetSymbolAddress((void**)&q2a,   g_q2a);
    cudaGetSymbolAddress((void**)&q2b,   g_q2b);
    cudaGetSymbolAddress((void**)&fx2,   g_fx2);
    cudaGetSymbolAddress((void**)&xs,    g_xs);
    cudaGetSymbolAddress((void**)&xes,   g_xes);
    cudaGetSymbolAddress((void**)&fxs,   g_fxs);
    cudaGetSymbolAddress((void**)&ball,  g_ball);

    // split inputs + weights into 6-segment bf16 K-extension
    splitAB_k<<<16384, 256>>>(x, xe, xs, xes);
    splitW_k<<<dim3(16, 56), dim3(32, 8)>>>(Wq, Wk, Wv, ball);

    // fused projections (heavy 6-limb tiles first; enc-V 3-limb tiles last)
    proj_k<<<448, 256>>>(xs, xes, ball, qkv, kvenc);

    // self-attention; writes split-extended fxs directly
    attn2_k<1, 0, 1><<<512, 512>>>(qkv, nullptr, 1024, 0, qkv, 1024, 256, 512, nullptr, fxs);

    // cross-attention Q projection (split-K=2 over segment halves)
    crossq_k<<<128, 256>>>(fxs, ball, q2a, q2b);

    // cross-attention (no mask), Q = q2a + q2b
    attn2_k<0, 1, 0><<<512, 512>>>(q2a, q2b, 256, 0, kvenc, 768, 0, 256, fx2, nullptr);

    // residual + LN + FFN
    lnffn_k<<<4096, 256>>>(x, fx2, lg, lb, w1, b1, w2, b2, out);
}

// round 12
// speedup vs baseline: 1.0579x; 1.0579x over previous
#include <cuda_runtime.h>
#include <cuda_bf16.h>
#include <cstdint>

#define BS 8
#define SEQ 512
#define DM 512
#define NROW (BS*SEQ)          // 4096
#define KEXT 3072              // 6 segments x 512

// ---------------- scratch (no allocation allowed) ----------------
__device__ __align__(16) float g_qkv[NROW * 1024];    // [Q(256)|K(256)|V(512)] self
__device__ __align__(16) float g_kvenc[NROW * 768];   // [K(256)|V(512)] encoder
__device__ __align__(16) float g_q2a[NROW * 256];     // cross-Q split-K partial 0
__device__ __align__(16) float g_q2b[NROW * 256];     // cross-Q split-K partial 1
__device__ __align__(16) float g_fx2[NROW * 512];     // cross-attn output
__device__ __align__(16) __nv_bfloat16 g_xs [NROW * KEXT];   // x   split-extended
__device__ __align__(16) __nv_bfloat16 g_xes[NROW * KEXT];   // xe  split-extended
__device__ __align__(16) __nv_bfloat16 g_fxs[NROW * KEXT];   // fx  split-extended
__device__ __align__(16) __nv_bfloat16 g_ball[1792 * KEXT];  // [Wq|Wk|Wv|Wk|Wv]^T split

// ---------------- helpers ----------------
__device__ __forceinline__ uint32_t smem_u32(const void* p) {
    uint32_t a;
    asm("{ .reg .u64 t; cvta.to.shared.u64 t, %1; cvt.u32.u64 %0, t; }" : "=r"(a) : "l"(p));
    return a;
}
__device__ __forceinline__ float ex2(float x) {
    float y; asm("ex2.approx.f32 %0, %1;" : "=f"(y) : "f"(x)); return y;
}
__device__ __forceinline__ unsigned long long pk2(float x, float y) {
    unsigned long long r; asm("mov.b64 %0, {%1,%2};" : "=l"(r) : "f"(x), "f"(y)); return r;
}
__device__ __forceinline__ void fma2(unsigned long long& d, unsigned long long a, unsigned long long b) {
    asm("fma.rn.f32x2 %0, %1, %2, %0;" : "+l"(d) : "l"(a), "l"(b));
}
__device__ __forceinline__ void mul2(unsigned long long& d, unsigned long long a) {
    asm("mul.rn.f32x2 %0, %0, %1;" : "+l"(d) : "l"(a));
}
__device__ __forceinline__ float2 up2(unsigned long long v) {
    float2 r; asm("mov.b64 {%0,%1}, %2;" : "=f"(r.x), "=f"(r.y) : "l"(v)); return r;
}
__device__ __forceinline__ void cpasync16(uint32_t dst, const void* src) {
    asm volatile("cp.async.cg.shared.global [%0], [%1], 16;" :: "r"(dst), "l"(src));
}

__device__ __forceinline__ void split3(float v, __nv_bfloat16& h, __nv_bfloat16& m, __nv_bfloat16& l) {
    h = __float2bfloat16(v);
    float r1 = v - __bfloat162float(h);
    m = __float2bfloat16(r1);
    float r2 = r1 - __bfloat162float(m);
    l = __float2bfloat16(r2);
}

// ---------------- split kernels ----------------
// A segments: [hi, hi, mid, hi, lo, mid]; handles x and xe in one launch.
__global__ __launch_bounds__(256) void splitAB_k(const float* __restrict__ x, const float* __restrict__ xe,
                                                 __nv_bfloat16* __restrict__ xs, __nv_bfloat16* __restrict__ xes)
{
    int gid = blockIdx.x * 256 + threadIdx.x;   // 2 * NROW*512
    const float* in; __nv_bfloat16* out; int id;
    if (gid < NROW * 512) { in = x; out = xs; id = gid; }
    else { in = xe; out = xes; id = gid - NROW * 512; }
    int r = id >> 9, c = id & 511;
    __nv_bfloat16 h, m, l;
    split3(in[id], h, m, l);
    __nv_bfloat16* o = out + (size_t)r * KEXT + c;
    o[0] = h; o[512] = h; o[1024] = m; o[1536] = h; o[2048] = l; o[2560] = m;
}

// B rows: g_ball[n][k] = W[k][n], segments [hi, mid, hi, lo, hi, mid]
__global__ void splitW_k(const float* __restrict__ Wq, const float* __restrict__ Wk,
                         const float* __restrict__ Wv, __nv_bfloat16* __restrict__ out)
{
    __shared__ float s[32][33];
    const int k0 = blockIdx.x * 32, n0 = blockIdx.y * 32;
    const int tx = threadIdx.x, ty = threadIdx.y;   // 32 x 8

    const float* src; int col0, ldw;
    if      (n0 < 256)  { src = Wq; col0 = n0;        ldw = 256; }
    else if (n0 < 512)  { src = Wk; col0 = n0 - 256;  ldw = 256; }
    else if (n0 < 1024) { src = Wv; col0 = n0 - 512;  ldw = 512; }
    else if (n0 < 1280) { src = Wk; col0 = n0 - 1024; ldw = 256; }
    else                { src = Wv; col0 = n0 - 1280; ldw = 512; }

#pragma unroll
    for (int i = 0; i < 4; i++) {
        int kk = ty + i * 8;
        s[kk][tx] = src[(k0 + kk) * ldw + col0 + tx];
    }
    __syncthreads();
#pragma unroll
    for (int i = 0; i < 4; i++) {
        int nn = ty + i * 8;
        __nv_bfloat16 h, m, l;
        split3(s[tx][nn], h, m, l);
        __nv_bfloat16* o = out + (size_t)(n0 + nn) * KEXT + k0 + tx;
        o[0] = h; o[512] = m; o[1024] = h; o[1536] = l; o[2048] = h; o[2560] = m;
    }
}

// ---------------- mma.sync GEMM body: 128x128 CTA tile, KC=32 ----------------
struct SmemMM {
    __nv_bfloat16 sA[2][128][40];   // 40 = 32 + pad (conflict-free)
    __nv_bfloat16 sB[2][128][40];
};

__device__ __forceinline__ void mma_body(SmemMM& sm,
    const __nv_bfloat16* __restrict__ A, const __nv_bfloat16* __restrict__ B,
    float* __restrict__ C, int ldc, int nch)
{
    const int tid = threadIdx.x;
    const int wid = tid >> 5, lane = tid & 31;

    const uint32_t sAb = smem_u32(&sm.sA[0][0][0]);
    const uint32_t sBb = smem_u32(&sm.sB[0][0][0]);
    const uint32_t STAGE = 128 * 80;

    auto issue = [&](int c, int buf) {
#pragma unroll
        for (int i = 0; i < 2; i++) {
            int g = tid + i * 256;
            int r = g >> 2, j = g & 3;
            uint32_t so = (uint32_t)buf * STAGE + r * 80 + j * 16;
            cpasync16(sAb + so, (const char*)(A + (size_t)r * KEXT + c * 32 + j * 8));
            cpasync16(sBb + so, (const char*)(B + (size_t)r * KEXT + c * 32 + j * 8));
        }
    };

    issue(0, 0);
    asm volatile("cp.async.commit_group;" ::: "memory");
    issue(1, 1);
    asm volatile("cp.async.commit_group;" ::: "memory");

    float acc[4][4][4];
#pragma unroll
    for (int i = 0; i < 4; i++)
#pragma unroll
        for (int j = 0; j < 4; j++)
#pragma unroll
            for (int k = 0; k < 4; k++) acc[i][j][k] = 0.f;

    const int wm = wid >> 2, wn = wid & 3;
    const int rbase = wm * 64 + (lane >> 2);
    const int nbase = wn * 32 + (lane >> 2);
    const int lq = lane & 3;

    for (int c = 0; c < nch; c++) {
        asm volatile("cp.async.wait_group 1;" ::: "memory");
        __syncthreads();
        const uint32_t* sA32 = (const uint32_t*)&sm.sA[c & 1][0][0];
        const uint32_t* sB32 = (const uint32_t*)&sm.sB[c & 1][0][0];

#pragma unroll
        for (int ks = 0; ks < 2; ks++) {
            const int cw = ks * 8 + lq;
            uint32_t af[4][4], bf[4][2];
#pragma unroll
            for (int am = 0; am < 4; am++) {
                int r = rbase + am * 16;
                af[am][0] = sA32[r * 20 + cw];
                af[am][1] = sA32[(r + 8) * 20 + cw];
                af[am][2] = sA32[r * 20 + cw + 4];
                af[am][3] = sA32[(r + 8) * 20 + cw + 4];
            }
#pragma unroll
            for (int an = 0; an < 4; an++) {
                int n = nbase + an * 8;
                bf[an][0] = sB32[n * 20 + cw];
                bf[an][1] = sB32[n * 20 + cw + 4];
            }
#pragma unroll
            for (int am = 0; am < 4; am++)
#pragma unroll
                for (int an = 0; an < 4; an++) {
                    asm volatile(
                        "mma.sync.aligned.m16n8k16.row.col.f32.bf16.bf16.f32 "
                        "{%0,%1,%2,%3}, {%4,%5,%6,%7}, {%8,%9}, {%0,%1,%2,%3};"
                        : "+f"(acc[am][an][0]), "+f"(acc[am][an][1]),
                          "+f"(acc[am][an][2]), "+f"(acc[am][an][3])
                        : "r"(af[am][0]), "r"(af[am][1]), "r"(af[am][2]), "r"(af[am][3]),
                          "r"(bf[an][0]), "r"(bf[an][1]));
                }
        }
        __syncthreads();
        if (c + 2 < nch) issue(c + 2, c & 1);
        asm volatile("cp.async.commit_group;" ::: "memory");
    }

#pragma unroll
    for (int am = 0; am < 4; am++) {
#pragma unroll
        for (int an = 0; an < 4; an++) {
            int r0 = wm * 64 + am * 16 + (lane >> 2);
            int cc = wn * 32 + an * 8 + lq * 2;
            *(float2*)&C[r0 * ldc + cc]       = make_float2(acc[am][an][0], acc[am][an][1]);
            *(float2*)&C[(r0 + 8) * ldc + cc] = make_float2(acc[am][an][2], acc[am][an][3]);
        }
    }
}

// fused projections, 448 blocks, heavy (6-limb) first, light (3-limb enc-V) last
__global__ __launch_bounds__(256, 2) void proj_k(
    const __nv_bfloat16* __restrict__ xs, const __nv_bfloat16* __restrict__ xes,
    const __nv_bfloat16* __restrict__ ball, float* __restrict__ qkv, float* __restrict__ kvenc)
{
    __shared__ SmemMM sm;
    const int bid = blockIdx.x;
    const __nv_bfloat16 *A, *B; float* C; int ldc, nch, bx, by;
    if (bid < 256) {
        bx = bid & 7; by = bid >> 3;
        A = xs; B = ball; C = qkv; ldc = 1024; nch = 96;
    } else if (bid < 320) {
        int i = bid - 256; bx = i & 1; by = i >> 1;
        A = xes; B = ball + (size_t)1024 * KEXT; C = kvenc; ldc = 768; nch = 96;
    } else {
        int i = bid - 320; bx = 2 + (i & 3); by = i >> 2;
        A = xes; B = ball + (size_t)1024 * KEXT; C = kvenc; ldc = 768; nch = 48;
    }
    mma_body(sm, A + (size_t)by * 128 * KEXT, B + (size_t)bx * 128 * KEXT,
             C + (size_t)by * 128 * ldc + bx * 128, ldc, nch);
}

// cross-Q GEMM: split-K=2 over the 6 segments: half0 = [h,h,m], half1 = [h,l,m]
__global__ __launch_bounds__(256, 2) void crossq_k(
    const __nv_bfloat16* __restrict__ fxs, const __nv_bfloat16* __restrict__ ball,
    float* __restrict__ q2a, float* __restrict__ q2b)
{
    __shared__ SmemMM sm;
    const int bid = blockIdx.x;            // 128
    const int half = bid >> 6;
    const int i = bid & 63;
    const int bx = i & 1, by = i >> 1;
    const __nv_bfloat16* A = fxs + half * 1536;
    const __nv_bfloat16* B = ball + half * 1536;
    float* C = half ? q2b : q2a;
    mma_body(sm, A + (size_t)by * 128 * KEXT, B + (size_t)bx * 128 * KEXT,
             C + (size_t)by * 128 * 256 + bx * 128, 256, 48);
}

// ---------------- CAUSAL attention: 1 query/thread, 2-pass (best-measured 105.8us) ----------------
__global__ __launch_bounds__(512, 2) void attnC_k(
    const float* __restrict__ QKV, __nv_bfloat16* __restrict__ OutS)
{
    __shared__ float sKt[4][512];                 // K transposed: [dim][key]
    __shared__ __align__(16) float sV[512 * 8];   // V row-major:  [key][dim]
    __shared__ float sWS[16][8];                  // warp V-sums for suffix scan

    const int bh = blockIdx.x;
    const int h = bh & 63, b = bh >> 6;
    const int t = threadIdx.x, lane = t & 31, wid = t >> 5;
    const int rowbase = b * SEQ + t;

    const float* kv = QKV + (size_t)rowbase * 1024;
    float4 kk = *(const float4*)(kv + 256 + h * 4);
    sKt[0][t] = kk.x; sKt[1][t] = kk.y; sKt[2][t] = kk.z; sKt[3][t] = kk.w;
    float4 v0 = *(const float4*)(kv + 512 + h * 8);
    float4 v1 = *(const float4*)(kv + 512 + h * 8 + 4);
    *(float4*)&sV[t * 8] = v0;
    *(float4*)&sV[t * 8 + 4] = v1;

    float suf[8];
    {
        float vown[8] = {v0.x, v0.y, v0.z, v0.w, v1.x, v1.y, v1.z, v1.w};
#pragma unroll
        for (int d = 0; d < 8; d++) suf[d] = vown[d];
#pragma unroll
        for (int off = 1; off < 32; off <<= 1) {
#pragma unroll
            for (int d = 0; d < 8; d++) {
                float o = __shfl_down_sync(0xffffffffu, suf[d], off);
                if (lane + off < 32) suf[d] += o;
            }
        }
        if (lane == 0) {
#pragma unroll
            for (int d = 0; d < 8; d++) sWS[wid][d] = suf[d];
        }
        __syncthreads();
        for (int w = wid + 1; w < 16; w++)
#pragma unroll
            for (int d = 0; d < 8; d++) suf[d] += sWS[w][d];
#pragma unroll
        for (int d = 0; d < 8; d++) suf[d] -= vown[d];   // sum_{k > t}
    }

    const int q = t;
    const float SCQ = 0.72134752044448170f;  // 0.5 * log2(e)
    float4 qv = *(const float4*)(QKV + (size_t)rowbase * 1024 + h * 4);
    const float qs0 = qv.x * SCQ, qs1 = qv.y * SCQ, qs2 = qv.z * SCQ, qs3 = qv.w * SCQ;
    unsigned long long aq0 = pk2(qs0, qs0), aq1 = pk2(qs1, qs1);
    unsigned long long aq2 = pk2(qs2, qs2), aq3 = pk2(qs3, qs3);

    const int n = q + 1;
    const int nquad = n >> 2;

    float m = 0.f;    // masked zeros participate
    for (int i = 0; i < nquad; i++) {
        const int k4 = i << 2;
        ulonglong2 k0 = *(const ulonglong2*)&sKt[0][k4];
        ulonglong2 k1 = *(const ulonglong2*)&sKt[1][k4];
        ulonglong2 k2 = *(const ulonglong2*)&sKt[2][k4];
        ulonglong2 k3 = *(const ulonglong2*)&sKt[3][k4];
        unsigned long long s01 = 0ULL, s23 = 0ULL;
        fma2(s01, aq0, k0.x); fma2(s23, aq0, k0.y);
        fma2(s01, aq1, k1.x); fma2(s23, aq1, k1.y);
        fma2(s01, aq2, k2.x); fma2(s23, aq2, k2.y);
        fma2(s01, aq3, k3.x); fma2(s23, aq3, k3.y);
        float2 f01 = up2(s01), f23 = up2(s23);
        m = fmaxf(m, fmaxf(fmaxf(f01.x, f01.y), fmaxf(f23.x, f23.y)));
    }
    for (int k = nquad << 2; k < n; k++) {
        float s = fmaf(qs0, sKt[0][k], fmaf(qs1, sKt[1][k], fmaf(qs2, sKt[2][k], qs3 * sKt[3][k])));
        m = fmaxf(m, s);
    }

    const unsigned long long nm = pk2(-m, -m);
    float denom = 0.f;
    unsigned long long acc0 = 0, acc1 = 0, acc2 = 0, acc3 = 0;
    for (int i = 0; i < nquad; i++) {
        const int k4 = i << 2;
        ulonglong2 k0 = *(const ulonglong2*)&sKt[0][k4];
        ulonglong2 k1 = *(const ulonglong2*)&sKt[1][k4];
        ulonglong2 k2 = *(const ulonglong2*)&sKt[2][k4];
        ulonglong2 k3 = *(const ulonglong2*)&sKt[3][k4];
        unsigned long long s01 = nm, s23 = nm;
        fma2(s01, aq0, k0.x); fma2(s23, aq0, k0.y);
        fma2(s01, aq1, k1.x); fma2(s23, aq1, k1.y);
        fma2(s01, aq2, k2.x); fma2(s23, aq2, k2.y);
        fma2(s01, aq3, k3.x); fma2(s23, aq3, k3.y);
        float2 f01 = up2(s01), f23 = up2(s23);
        float p0 = ex2(f01.x), p1 = ex2(f01.y), p2 = ex2(f23.x), p3 = ex2(f23.y);
        denom += (p0 + p1) + (p2 + p3);
        const float* vb = &sV[k4 * 8];
        {
            unsigned long long P = pk2(p0, p0);
            ulonglong2 va = *(const ulonglong2*)(vb);
            ulonglong2 vc = *(const ulonglong2*)(vb + 4);
            fma2(acc0, P, va.x); fma2(acc1, P, va.y); fma2(acc2, P, vc.x); fma2(acc3, P, vc.y);
        }
        {
            unsigned long long P = pk2(p1, p1);
            ulonglong2 va = *(const ulonglong2*)(vb + 8);
            ulonglong2 vc = *(const ulonglong2*)(vb + 12);
            fma2(acc0, P, va.x); fma2(acc1, P, va.y); fma2(acc2, P, vc.x); fma2(acc3, P, vc.y);
        }
        {
            unsigned long long P = pk2(p2, p2);
            ulonglong2 va = *(const ulonglong2*)(vb + 16);
            ulonglong2 vc = *(const ulonglong2*)(vb + 20);
            fma2(acc0, P, va.x); fma2(acc1, P, va.y); fma2(acc2, P, vc.x); fma2(acc3, P, vc.y);
        }
        {
            unsigned long long P = pk2(p3, p3);
            ulonglong2 va = *(const ulonglong2*)(vb + 24);
            ulonglong2 vc = *(const ulonglong2*)(vb + 28);
            fma2(acc0, P, va.x); fma2(acc1, P, va.y); fma2(acc2, P, vc.x); fma2(acc3, P, vc.y);
        }
    }
    for (int k = nquad << 2; k < n; k++) {
        float s = -m + fmaf(qs0, sKt[0][k], fmaf(qs1, sKt[1][k], fmaf(qs2, sKt[2][k], qs3 * sKt[3][k])));
        float p = ex2(s);
        denom += p;
        unsigned long long P = pk2(p, p);
        const float* vb = &sV[k * 8];
        ulonglong2 va = *(const ulonglong2*)(vb);
        ulonglong2 vc = *(const ulonglong2*)(vb + 4);
        fma2(acc0, P, va.x); fma2(acc1, P, va.y); fma2(acc2, P, vc.x); fma2(acc3, P, vc.y);
    }

    {
        float pm = ex2(-m);
        denom += (float)(SEQ - 1 - q) * pm;
        unsigned long long P = pk2(pm, pm);
        fma2(acc0, P, pk2(suf[0], suf[1]));
        fma2(acc1, P, pk2(suf[2], suf[3]));
        fma2(acc2, P, pk2(suf[4], suf[5]));
        fma2(acc3, P, pk2(suf[6], suf[7]));
    }

    const float inv = 1.0f / denom;
    float2 o0 = up2(acc0), o1 = up2(acc1), o2 = up2(acc2), o3 = up2(acc3);
    float vals[8] = {o0.x * inv, o0.y * inv, o1.x * inv, o1.y * inv,
                     o2.x * inv, o2.y * inv, o3.x * inv, o3.y * inv};

    // write split-extended bf16 rows (A segments [h,h,m,h,l,m]) directly
    __align__(16) __nv_bfloat16 H[8], M[8], L[8];
#pragma unroll
    for (int d = 0; d < 8; d++) split3(vals[d], H[d], M[d], L[d]);
    __nv_bfloat16* ob = OutS + (size_t)rowbase * KEXT + h * 8;
    *(uint4*)(ob)        = *(uint4*)H;
    *(uint4*)(ob + 512)  = *(uint4*)H;
    *(uint4*)(ob + 1024) = *(uint4*)M;
    *(uint4*)(ob + 1536) = *(uint4*)H;
    *(uint4*)(ob + 2048) = *(uint4*)L;
    *(uint4*)(ob + 2560) = *(uint4*)M;
}

// ---------------- NON-CAUSAL attention: 2 queries/thread, online softmax ----------------
// (best-measured cross kernel: K/V quads loaded once, used by q1=t and q2=t+256)
__global__ __launch_bounds__(256, 2) void attnX_k(
    const float* __restrict__ Qa, const float* __restrict__ Qb,
    const float* __restrict__ KVbuf, float* __restrict__ Out)
{
    __shared__ float sKt[4][512];                 // K transposed: [dim][key]
    __shared__ __align__(16) float sV[512 * 8];   // V row-major:  [key][dim]

    const int bh = blockIdx.x;
    const int h = bh & 63, b = bh >> 6;
    const int t = threadIdx.x;

#pragma unroll
    for (int rr = 0; rr < 2; rr++) {
        const int row = t + rr * 256;
        const float* kv = KVbuf + (size_t)(b * SEQ + row) * 768;
        float4 kk = *(const float4*)(kv + h * 4);
        sKt[0][row] = kk.x; sKt[1][row] = kk.y; sKt[2][row] = kk.z; sKt[3][row] = kk.w;
        float4 v0 = *(const float4*)(kv + 256 + h * 8);
        float4 v1 = *(const float4*)(kv + 256 + h * 8 + 4);
        *(float4*)&sV[row * 8] = v0;
        *(float4*)&sV[row * 8 + 4] = v1;
    }
    __syncthreads();

    const float SCQ = 0.72134752044448170f;  // 0.5 * log2(e)
    unsigned long long aq1[4], aq2[4];
#pragma unroll
    for (int rr = 0; rr < 2; rr++) {
        const size_t row = (size_t)(b * SEQ + t + rr * 256);
        float4 qv = *(const float4*)(Qa + row * 256 + h * 4);
        float4 q2v = *(const float4*)(Qb + row * 256 + h * 4);
        qv.x += q2v.x; qv.y += q2v.y; qv.z += q2v.z; qv.w += q2v.w;
        unsigned long long* aq = rr ? aq2 : aq1;
        aq[0] = pk2(qv.x * SCQ, qv.x * SCQ);
        aq[1] = pk2(qv.y * SCQ, qv.y * SCQ);
        aq[2] = pk2(qv.z * SCQ, qv.z * SCQ);
        aq[3] = pk2(qv.w * SCQ, qv.w * SCQ);
    }

    float m1 = -1e30f, m2 = -1e30f;
    float d1 = 0.f, d2 = 0.f;
    unsigned long long A1[4] = {0ULL, 0ULL, 0ULL, 0ULL};
    unsigned long long A2[4] = {0ULL, 0ULL, 0ULL, 0ULL};

    auto step = [&](const float* s, float& m, float& dn, unsigned long long* A,
                    const ulonglong2* vv) {
        float qm = fmaxf(fmaxf(s[0], s[1]), fmaxf(s[2], s[3]));
        if (qm > m) {
            float r = ex2(m - qm);
            m = qm; dn *= r;
            unsigned long long R = pk2(r, r);
            mul2(A[0], R); mul2(A[1], R); mul2(A[2], R); mul2(A[3], R);
        }
        float p0 = ex2(s[0] - m), p1 = ex2(s[1] - m);
        float p2 = ex2(s[2] - m), p3 = ex2(s[3] - m);
        dn += (p0 + p1) + (p2 + p3);
        unsigned long long P;
        P = pk2(p0, p0);
        fma2(A[0], P, vv[0].x); fma2(A[1], P, vv[0].y); fma2(A[2], P, vv[1].x); fma2(A[3], P, vv[1].y);
        P = pk2(p1, p1);
        fma2(A[0], P, vv[2].x); fma2(A[1], P, vv[2].y); fma2(A[2], P, vv[3].x); fma2(A[3], P, vv[3].y);
        P = pk2(p2, p2);
        fma2(A[0], P, vv[4].x); fma2(A[1], P, vv[4].y); fma2(A[2], P, vv[5].x); fma2(A[3], P, vv[5].y);
        P = pk2(p3, p3);
        fma2(A[0], P, vv[6].x); fma2(A[1], P, vv[6].y); fma2(A[2], P, vv[7].x); fma2(A[3], P, vv[7].y);
    };

    for (int i = 0; i < 128; i++) {
        const int k4 = i << 2;
        ulonglong2 kq[4], vv[8];
        kq[0] = *(const ulonglong2*)&sKt[0][k4];
        kq[1] = *(const ulonglong2*)&sKt[1][k4];
        kq[2] = *(const ulonglong2*)&sKt[2][k4];
        kq[3] = *(const ulonglong2*)&sKt[3][k4];
        const float* vb = &sV[k4 * 8];
#pragma unroll
        for (int j = 0; j < 4; j++) {
            vv[2 * j]     = *(const ulonglong2*)(vb + j * 8);
            vv[2 * j + 1] = *(const ulonglong2*)(vb + j * 8 + 4);
        }
        float s1[4], s2[4];
        {
            unsigned long long s01 = 0ULL, s23 = 0ULL;
            fma2(s01, aq1[0], kq[0].x); fma2(s23, aq1[0], kq[0].y);
            fma2(s01, aq1[1], kq[1].x); fma2(s23, aq1[1], kq[1].y);
            fma2(s01, aq1[2], kq[2].x); fma2(s23, aq1[2], kq[2].y);
            fma2(s01, aq1[3], kq[3].x); fma2(s23, aq1[3], kq[3].y);
            float2 f01 = up2(s01), f23 = up2(s23);
            s1[0] = f01.x; s1[1] = f01.y; s1[2] = f23.x; s1[3] = f23.y;
        }
        {
            unsigned long long s01 = 0ULL, s23 = 0ULL;
            fma2(s01, aq2[0], kq[0].x); fma2(s23, aq2[0], kq[0].y);
            fma2(s01, aq2[1], kq[1].x); fma2(s23, aq2[1], kq[1].y);
            fma2(s01, aq2[2], kq[2].x); fma2(s23, aq2[2], kq[2].y);
            fma2(s01, aq2[3], kq[3].x); fma2(s23, aq2[3], kq[3].y);
            float2 f01 = up2(s01), f23 = up2(s23);
            s2[0] = f01.x; s2[1] = f01.y; s2[2] = f23.x; s2[3] = f23.y;
        }
        step(s1, m1, d1, A1, vv);
        step(s2, m2, d2, A2, vv);
    }

#pragma unroll
    for (int rr = 0; rr < 2; rr++) {
        const unsigned long long* A = rr ? A2 : A1;
        const float inv = 1.0f / (rr ? d2 : d1);
        float2 o0 = up2(A[0]), o1 = up2(A[1]), o2 = up2(A[2]), o3 = up2(A[3]);
        float* o = Out + (size_t)(b * SEQ + t + rr * 256) * DM + h * 8;
        *(float4*)(o)     = make_float4(o0.x * inv, o0.y * inv, o1.x * inv, o1.y * inv);
        *(float4*)(o + 4) = make_float4(o2.x * inv, o2.y * inv, o3.x * inv, o3.y * inv);
    }
}

// ---------------- Residual + LayerNorm + FFN (hidden=10) fused ----------------
#define HIDD 10
__global__ __launch_bounds__(256) void lnffn_k(
    const float* __restrict__ x, const float* __restrict__ fx,
    const float* __restrict__ lg, const float* __restrict__ lb,
    const float* __restrict__ w1, const float* __restrict__ b1,
    const float* __restrict__ w2, const float* __restrict__ b2,
    float* __restrict__ out)
{
    const int row = blockIdx.x;
    const int t = threadIdx.x;
    const int warp = t >> 5, lane = t & 31;

    const float* xr = x + row * DM;
    const float* fr = fx + row * DM;
    float v0 = xr[t] + fr[t];
    float v1 = xr[t + 256] + fr[t + 256];

    float s = v0 + v1;
    float ss = v0 * v0 + v1 * v1;
#pragma unroll
    for (int o = 16; o > 0; o >>= 1) {
        s  += __shfl_down_sync(0xffffffffu, s,  o);
        ss += __shfl_down_sync(0xffffffffu, ss, o);
    }
    __shared__ float rs[8], rss[8];
    if (lane == 0) { rs[warp] = s; rss[warp] = ss; }
    __syncthreads();
    float S = 0.f, SS = 0.f;
#pragma unroll
    for (int w = 0; w < 8; w++) { S += rs[w]; SS += rss[w]; }
    const float mu = S * (1.0f / DM);
    const float var = SS * (1.0f / DM) - mu * mu;
    const float rstd = rsqrtf(var + 1e-5f);

    const float y0 = (v0 - mu) * rstd * lg[t] + lb[t];
    const float y1 = (v1 - mu) * rstd * lg[t + 256] + lb[t + 256];

    float pj[HIDD];
#pragma unroll
    for (int j = 0; j < HIDD; j++)
        pj[j] = y0 * __ldg(&w1[j * DM + t]) + y1 * __ldg(&w1[j * DM + t + 256]);
#pragma unroll
    for (int j = 0; j < HIDD; j++)
#pragma unroll
        for (int o = 16; o > 0; o >>= 1)
            pj[j] += __shfl_down_sync(0xffffffffu, pj[j], o);

    __shared__ float hred[8][HIDD];
    if (lane == 0)
#pragma unroll
        for (int j = 0; j < HIDD; j++) hred[warp][j] = pj[j];
    __syncthreads();

    __shared__ float sh[HIDD];
    if (t < HIDD) {
        float hv = b1[t];
#pragma unroll
        for (int w = 0; w < 8; w++) hv += hred[w][t];
        sh[t] = fmaxf(hv, 0.f);
    }
    __syncthreads();

    float o0 = b2[t], o1 = b2[t + 256];
#pragma unroll
    for (int j = 0; j < HIDD; j++) {
        const float hj = sh[j];
        o0 = fmaf(hj, __ldg(&w2[t * HIDD + j]), o0);
        o1 = fmaf(hj, __ldg(&w2[(t + 256) * HIDD + j]), o1);
    }
    out[row * DM + t] = o0;
    out[row * DM + t + 256] = o1;
}

// ---------------- launch ----------------
extern "C" void kernel_launch(void* const* d_in, const int* in_sizes, int n_in,
                              void* d_out, int out_size)
{
    const float* x   = (const float*)d_in[0];
    const float* xe  = (const float*)d_in[1];
    const float* Wq  = (const float*)d_in[2];
    const float* Wk  = (const float*)d_in[3];
    const float* Wv  = (const float*)d_in[4];
    const float* lg  = (const float*)d_in[5];
    const float* lb  = (const float*)d_in[6];
    const float* w1  = (const float*)d_in[7];
    const float* b1  = (const float*)d_in[8];
    const float* w2  = (const float*)d_in[9];
    const float* b2  = (const float*)d_in[10];
    float* out = (float*)d_out;

    float *qkv, *kvenc, *q2a, *q2b, *fx2;
    __nv_bfloat16 *xs, *xes, *fxs, *ball;
    cudaGetSymbolAddress((void**)&qkv,   g_qkv);
    cudaGetSymbolAddress((void**)&kvenc, g_kvenc);
    cudaGetSymbolAddress((void**)&q2a,   g_q2a);
    cudaGetSymbolAddress((void**)&q2b,   g_q2b);
    cudaGetSymbolAddress((void**)&fx2,   g_fx2);
    cudaGetSymbolAddress((void**)&xs,    g_xs);
    cudaGetSymbolAddress((void**)&xes,   g_xes);
    cudaGetSymbolAddress((void**)&fxs,   g_fxs);
    cudaGetSymbolAddress((void**)&ball,  g_ball);

    // split inputs + weights into 6-segment bf16 K-extension
    splitAB_k<<<16384, 256>>>(x, xe, xs, xes);
    splitW_k<<<dim3(16, 56), dim3(32, 8)>>>(Wq, Wk, Wv, ball);

    // fused projections (heavy 6-limb tiles first; enc-V 3-limb tiles last)
    proj_k<<<448, 256>>>(xs, xes, ball, qkv, kvenc);

    // self-attention (1q/thread, 2-pass; best-measured); writes split-extended fxs
    attnC_k<<<512, 512>>>(qkv, fxs);

    // cross-attention Q projection (split-K=2 over segment halves)
    crossq_k<<<128, 256>>>(fxs, ball, q2a, q2b);

    // cross-attention (2q/thread online; best-measured), Q = q2a + q2b
    attnX_k<<<512, 256>>>(q2a, q2b, kvenc, fx2);

    // residual + LN + FFN
    lnffn_k<<<4096, 256>>>(x, fx2, lg, lb, w1, b1, w2, b2, out);
}

// round 13
// speedup vs baseline: 1.1185x; 1.0573x over previous
#include <cuda_runtime.h>
#include <cuda_bf16.h>
#include <cstdint>

#define BS 8
#define SEQ 512
#define DM 512
#define NROW (BS*SEQ)          // 4096
#define KEXT 3072              // 6 segments x 512
#define KC 64                  // GEMM k-chunk

// ---------------- scratch (no allocation allowed) ----------------
__device__ __align__(16) float g_qkv[NROW * 1024];    // [Q(256)|K(256)|V(512)] self
__device__ __align__(16) float g_kvenc[NROW * 768];   // [K(256)|V(512)] encoder
__device__ __align__(16) float g_q2a[NROW * 256];     // cross-Q split-K partial 0
__device__ __align__(16) float g_q2b[NROW * 256];     // cross-Q split-K partial 1
__device__ __align__(16) float g_fx2[NROW * 512];     // cross-attn output
__device__ __align__(16) __nv_bfloat16 g_xs [NROW * KEXT];   // x   split-extended
__device__ __align__(16) __nv_bfloat16 g_xes[NROW * KEXT];   // xe  split-extended
__device__ __align__(16) __nv_bfloat16 g_fxs[NROW * KEXT];   // fx  split-extended
__device__ __align__(16) __nv_bfloat16 g_ball[1792 * KEXT];  // [Wq|Wk|Wv|Wk|Wv]^T split

// ---------------- helpers ----------------
__device__ __forceinline__ uint32_t smem_u32(const void* p) {
    uint32_t a;
    asm("{ .reg .u64 t; cvta.to.shared.u64 t, %1; cvt.u32.u64 %0, t; }" : "=r"(a) : "l"(p));
    return a;
}
__device__ __forceinline__ float ex2(float x) {
    float y; asm("ex2.approx.f32 %0, %1;" : "=f"(y) : "f"(x)); return y;
}
__device__ __forceinline__ unsigned long long pk2(float x, float y) {
    unsigned long long r; asm("mov.b64 %0, {%1,%2};" : "=l"(r) : "f"(x), "f"(y)); return r;
}
__device__ __forceinline__ void fma2(unsigned long long& d, unsigned long long a, unsigned long long b) {
    asm("fma.rn.f32x2 %0, %1, %2, %0;" : "+l"(d) : "l"(a), "l"(b));
}
__device__ __forceinline__ void mul2(unsigned long long& d, unsigned long long a) {
    asm("mul.rn.f32x2 %0, %0, %1;" : "+l"(d) : "l"(a));
}
__device__ __forceinline__ float2 up2(unsigned long long v) {
    float2 r; asm("mov.b64 {%0,%1}, %2;" : "=f"(r.x), "=f"(r.y) : "l"(v)); return r;
}
__device__ __forceinline__ void cpasync16(uint32_t dst, const void* src) {
    asm volatile("cp.async.cg.shared.global [%0], [%1], 16;" :: "r"(dst), "l"(src));
}
__device__ __forceinline__ void ldsm4(uint32_t& r0, uint32_t& r1, uint32_t& r2, uint32_t& r3, uint32_t addr) {
    asm volatile("ldmatrix.sync.aligned.m8n8.x4.shared.b16 {%0,%1,%2,%3}, [%4];"
                 : "=r"(r0), "=r"(r1), "=r"(r2), "=r"(r3) : "r"(addr));
}

__device__ __forceinline__ void split3(float v, __nv_bfloat16& h, __nv_bfloat16& m, __nv_bfloat16& l) {
    h = __float2bfloat16(v);
    float r1 = v - __bfloat162float(h);
    m = __float2bfloat16(r1);
    float r2 = r1 - __bfloat162float(m);
    l = __float2bfloat16(r2);
}

// ---------------- split kernels ----------------
// A segments: [hi, hi, mid, hi, lo, mid]; handles x and xe in one launch.
__global__ __launch_bounds__(256) void splitAB_k(const float* __restrict__ x, const float* __restrict__ xe,
                                                 __nv_bfloat16* __restrict__ xs, __nv_bfloat16* __restrict__ xes)
{
    int gid = blockIdx.x * 256 + threadIdx.x;   // 2 * NROW*512
    const float* in; __nv_bfloat16* out; int id;
    if (gid < NROW * 512) { in = x; out = xs; id = gid; }
    else { in = xe; out = xes; id = gid - NROW * 512; }
    int r = id >> 9, c = id & 511;
    __nv_bfloat16 h, m, l;
    split3(in[id], h, m, l);
    __nv_bfloat16* o = out + (size_t)r * KEXT + c;
    o[0] = h; o[512] = h; o[1024] = m; o[1536] = h; o[2048] = l; o[2560] = m;
}

// B rows: g_ball[n][k] = W[k][n], segments [hi, mid, hi, lo, hi, mid]
__global__ void splitW_k(const float* __restrict__ Wq, const float* __restrict__ Wk,
                         const float* __restrict__ Wv, __nv_bfloat16* __restrict__ out)
{
    __shared__ float s[32][33];
    const int k0 = blockIdx.x * 32, n0 = blockIdx.y * 32;
    const int tx = threadIdx.x, ty = threadIdx.y;   // 32 x 8

    const float* src; int col0, ldw;
    if      (n0 < 256)  { src = Wq; col0 = n0;        ldw = 256; }
    else if (n0 < 512)  { src = Wk; col0 = n0 - 256;  ldw = 256; }
    else if (n0 < 1024) { src = Wv; col0 = n0 - 512;  ldw = 512; }
    else if (n0 < 1280) { src = Wk; col0 = n0 - 1024; ldw = 256; }
    else                { src = Wv; col0 = n0 - 1280; ldw = 512; }

#pragma unroll
    for (int i = 0; i < 4; i++) {
        int kk = ty + i * 8;
        s[kk][tx] = src[(k0 + kk) * ldw + col0 + tx];
    }
    __syncthreads();
#pragma unroll
    for (int i = 0; i < 4; i++) {
        int nn = ty + i * 8;
        __nv_bfloat16 h, m, l;
        split3(s[tx][nn], h, m, l);
        __nv_bfloat16* o = out + (size_t)(n0 + nn) * KEXT + k0 + tx;
        o[0] = h; o[512] = m; o[1024] = h; o[1536] = l; o[2048] = h; o[2560] = m;
    }
}

// ---------------- mma.sync GEMM body: 128x128 CTA tile, KC=64, ldmatrix ----------------
// (best-measured GEMM: R9 ledger isolation shows ~23us faster than KC32 variant)
#define ROWB 144                     // 72 bf16 per row (64 + 8 pad), bytes
#define STAGE_B (128 * ROWB)         // bytes per stage per matrix
#define SMEM_MM (4 * STAGE_B)        // total dynamic smem (73728)

__device__ __forceinline__ void mma_body(char* smem,
    const __nv_bfloat16* __restrict__ A, const __nv_bfloat16* __restrict__ B,
    float* __restrict__ C, int ldc, int nch)
{
    const int tid = threadIdx.x;
    const int wid = tid >> 5, lane = tid & 31;

    const uint32_t sAb = smem_u32(smem);
    const uint32_t sBb = sAb + 2 * STAGE_B;

    auto issue = [&](int c, int buf) {
#pragma unroll
        for (int i = 0; i < 4; i++) {
            int g = tid + i * 256;           // 1024 granules of 16B
            int r = g >> 3, j = g & 7;
            uint32_t so = (uint32_t)buf * STAGE_B + r * ROWB + j * 16;
            cpasync16(sAb + so, (const char*)(A + (size_t)r * KEXT + c * KC + j * 8));
            cpasync16(sBb + so, (const char*)(B + (size_t)r * KEXT + c * KC + j * 8));
        }
    };

    issue(0, 0);
    asm volatile("cp.async.commit_group;" ::: "memory");
    issue(1, 1);
    asm volatile("cp.async.commit_group;" ::: "memory");

    float acc[4][4][4];
#pragma unroll
    for (int i = 0; i < 4; i++)
#pragma unroll
        for (int j = 0; j < 4; j++)
#pragma unroll
            for (int k = 0; k < 4; k++) acc[i][j][k] = 0.f;

    const int wm = wid >> 2, wn = wid & 3;
    const uint32_t lrow = lane & 15, lhalf = lane >> 4;
    const uint32_t aoff = (wm * 64 + lrow) * ROWB + lhalf * 16;
    const uint32_t boff = (wn * 32 + lrow) * ROWB + lhalf * 16;

    for (int c = 0; c < nch; c++) {
        asm volatile("cp.async.wait_group 1;" ::: "memory");
        __syncthreads();
        const uint32_t sa = sAb + (uint32_t)(c & 1) * STAGE_B + aoff;
        const uint32_t sb = sBb + (uint32_t)(c & 1) * STAGE_B + boff;

#pragma unroll
        for (int ks = 0; ks < 4; ks++) {
            uint32_t af[4][4], bf[4][2];
#pragma unroll
            for (int am = 0; am < 4; am++)
                ldsm4(af[am][0], af[am][1], af[am][2], af[am][3],
                      sa + am * 16 * ROWB + ks * 32);
#pragma unroll
            for (int anp = 0; anp < 2; anp++) {
                uint32_t r0, r1, r2, r3;
                ldsm4(r0, r1, r2, r3, sb + anp * 16 * ROWB + ks * 32);
                bf[2 * anp][0] = r0; bf[2 * anp + 1][0] = r1;
                bf[2 * anp][1] = r2; bf[2 * anp + 1][1] = r3;
            }
#pragma unroll
            for (int am = 0; am < 4; am++)
#pragma unroll
                for (int an = 0; an < 4; an++) {
                    asm volatile(
                        "mma.sync.aligned.m16n8k16.row.col.f32.bf16.bf16.f32 "
                        "{%0,%1,%2,%3}, {%4,%5,%6,%7}, {%8,%9}, {%0,%1,%2,%3};"
                        : "+f"(acc[am][an][0]), "+f"(acc[am][an][1]),
                          "+f"(acc[am][an][2]), "+f"(acc[am][an][3])
                        : "r"(af[am][0]), "r"(af[am][1]), "r"(af[am][2]), "r"(af[am][3]),
                          "r"(bf[an][0]), "r"(bf[an][1]));
                }
        }
        __syncthreads();
        if (c + 2 < nch) issue(c + 2, c & 1);
        asm volatile("cp.async.commit_group;" ::: "memory");
    }

#pragma unroll
    for (int am = 0; am < 4; am++) {
#pragma unroll
        for (int an = 0; an < 4; an++) {
            int r0 = wm * 64 + am * 16 + (lane >> 2);
            int cc = wn * 32 + an * 8 + (lane & 3) * 2;
            *(float2*)&C[r0 * ldc + cc]       = make_float2(acc[am][an][0], acc[am][an][1]);
            *(float2*)&C[(r0 + 8) * ldc + cc] = make_float2(acc[am][an][2], acc[am][an][3]);
        }
    }
}

// fused projections, 448 blocks, heavy (6-limb) first, light (3-limb enc-V) last
__global__ __launch_bounds__(256, 2) void proj_k(
    const __nv_bfloat16* __restrict__ xs, const __nv_bfloat16* __restrict__ xes,
    const __nv_bfloat16* __restrict__ ball, float* __restrict__ qkv, float* __restrict__ kvenc)
{
    extern __shared__ char smem[];
    const int bid = blockIdx.x;
    const __nv_bfloat16 *A, *B; float* C; int ldc, nch, bx, by;
    if (bid < 256) {
        bx = bid & 7; by = bid >> 3;
        A = xs; B = ball; C = qkv; ldc = 1024; nch = 48;
    } else if (bid < 320) {
        int i = bid - 256; bx = i & 1; by = i >> 1;
        A = xes; B = ball + (size_t)1024 * KEXT; C = kvenc; ldc = 768; nch = 48;
    } else {
        int i = bid - 320; bx = 2 + (i & 3); by = i >> 2;
        A = xes; B = ball + (size_t)1024 * KEXT; C = kvenc; ldc = 768; nch = 24;
    }
    mma_body(smem, A + (size_t)by * 128 * KEXT, B + (size_t)bx * 128 * KEXT,
             C + (size_t)by * 128 * ldc + bx * 128, ldc, nch);
}

// cross-Q GEMM: split-K=2 over the 6 segments: half0 = [h,h,m], half1 = [h,l,m]
__global__ __launch_bounds__(256, 2) void crossq_k(
    const __nv_bfloat16* __restrict__ fxs, const __nv_bfloat16* __restrict__ ball,
    float* __restrict__ q2a, float* __restrict__ q2b)
{
    extern __shared__ char smem[];
    const int bid = blockIdx.x;            // 128
    const int half = bid >> 6;
    const int i = bid & 63;
    const int bx = i & 1, by = i >> 1;
    const __nv_bfloat16* A = fxs + half * 1536;
    const __nv_bfloat16* B = ball + half * 1536;
    float* C = half ? q2b : q2a;
    mma_body(smem, A + (size_t)by * 128 * KEXT, B + (size_t)bx * 128 * KEXT,
             C + (size_t)by * 128 * 256 + bx * 128, 256, 24);
}

// ---------------- CAUSAL attention: 1 query/thread, 2-pass (best-measured) ----------------
__global__ __launch_bounds__(512, 2) void attnC_k(
    const float* __restrict__ QKV, __nv_bfloat16* __restrict__ OutS)
{
    __shared__ float sKt[4][512];                 // K transposed: [dim][key]
    __shared__ __align__(16) float sV[512 * 8];   // V row-major:  [key][dim]
    __shared__ float sWS[16][8];                  // warp V-sums for suffix scan

    const int bh = blockIdx.x;
    const int h = bh & 63, b = bh >> 6;
    const int t = threadIdx.x, lane = t & 31, wid = t >> 5;
    const int rowbase = b * SEQ + t;

    const float* kv = QKV + (size_t)rowbase * 1024;
    float4 kk = *(const float4*)(kv + 256 + h * 4);
    sKt[0][t] = kk.x; sKt[1][t] = kk.y; sKt[2][t] = kk.z; sKt[3][t] = kk.w;
    float4 v0 = *(const float4*)(kv + 512 + h * 8);
    float4 v1 = *(const float4*)(kv + 512 + h * 8 + 4);
    *(float4*)&sV[t * 8] = v0;
    *(float4*)&sV[t * 8 + 4] = v1;

    float suf[8];
    {
        float vown[8] = {v0.x, v0.y, v0.z, v0.w, v1.x, v1.y, v1.z, v1.w};
#pragma unroll
        for (int d = 0; d < 8; d++) suf[d] = vown[d];
#pragma unroll
        for (int off = 1; off < 32; off <<= 1) {
#pragma unroll
            for (int d = 0; d < 8; d++) {
                float o = __shfl_down_sync(0xffffffffu, suf[d], off);
                if (lane + off < 32) suf[d] += o;
            }
        }
        if (lane == 0) {
#pragma unroll
            for (int d = 0; d < 8; d++) sWS[wid][d] = suf[d];
        }
        __syncthreads();
        for (int w = wid + 1; w < 16; w++)
#pragma unroll
            for (int d = 0; d < 8; d++) suf[d] += sWS[w][d];
#pragma unroll
        for (int d = 0; d < 8; d++) suf[d] -= vown[d];   // sum_{k > t}
    }

    const int q = t;
    const float SCQ = 0.72134752044448170f;  // 0.5 * log2(e)
    float4 qv = *(const float4*)(QKV + (size_t)rowbase * 1024 + h * 4);
    const float qs0 = qv.x * SCQ, qs1 = qv.y * SCQ, qs2 = qv.z * SCQ, qs3 = qv.w * SCQ;
    unsigned long long aq0 = pk2(qs0, qs0), aq1 = pk2(qs1, qs1);
    unsigned long long aq2 = pk2(qs2, qs2), aq3 = pk2(qs3, qs3);

    const int n = q + 1;
    const int nquad = n >> 2;

    float m = 0.f;    // masked zeros participate
    for (int i = 0; i < nquad; i++) {
        const int k4 = i << 2;
        ulonglong2 k0 = *(const ulonglong2*)&sKt[0][k4];
        ulonglong2 k1 = *(const ulonglong2*)&sKt[1][k4];
        ulonglong2 k2 = *(const ulonglong2*)&sKt[2][k4];
        ulonglong2 k3 = *(const ulonglong2*)&sKt[3][k4];
        unsigned long long s01 = 0ULL, s23 = 0ULL;
        fma2(s01, aq0, k0.x); fma2(s23, aq0, k0.y);
        fma2(s01, aq1, k1.x); fma2(s23, aq1, k1.y);
        fma2(s01, aq2, k2.x); fma2(s23, aq2, k2.y);
        fma2(s01, aq3, k3.x); fma2(s23, aq3, k3.y);
        float2 f01 = up2(s01), f23 = up2(s23);
        m = fmaxf(m, fmaxf(fmaxf(f01.x, f01.y), fmaxf(f23.x, f23.y)));
    }
    for (int k = nquad << 2; k < n; k++) {
        float s = fmaf(qs0, sKt[0][k], fmaf(qs1, sKt[1][k], fmaf(qs2, sKt[2][k], qs3 * sKt[3][k])));
        m = fmaxf(m, s);
    }

    const unsigned long long nm = pk2(-m, -m);
    float denom = 0.f;
    unsigned long long acc0 = 0, acc1 = 0, acc2 = 0, acc3 = 0;
    for (int i = 0; i < nquad; i++) {
        const int k4 = i << 2;
        ulonglong2 k0 = *(const ulonglong2*)&sKt[0][k4];
        ulonglong2 k1 = *(const ulonglong2*)&sKt[1][k4];
        ulonglong2 k2 = *(const ulonglong2*)&sKt[2][k4];
        ulonglong2 k3 = *(const ulonglong2*)&sKt[3][k4];
        unsigned long long s01 = nm, s23 = nm;
        fma2(s01, aq0, k0.x); fma2(s23, aq0, k0.y);
        fma2(s01, aq1, k1.x); fma2(s23, aq1, k1.y);
        fma2(s01, aq2, k2.x); fma2(s23, aq2, k2.y);
        fma2(s01, aq3, k3.x); fma2(s23, aq3, k3.y);
        float2 f01 = up2(s01), f23 = up2(s23);
        float p0 = ex2(f01.x), p1 = ex2(f01.y), p2 = ex2(f23.x), p3 = ex2(f23.y);
        denom += (p0 + p1) + (p2 + p3);
        const float* vb = &sV[k4 * 8];
        {
            unsigned long long P = pk2(p0, p0);
            ulonglong2 va = *(const ulonglong2*)(vb);
            ulonglong2 vc = *(const ulonglong2*)(vb + 4);
            fma2(acc0, P, va.x); fma2(acc1, P, va.y); fma2(acc2, P, vc.x); fma2(acc3, P, vc.y);
        }
        {
            unsigned long long P = pk2(p1, p1);
            ulonglong2 va = *(const ulonglong2*)(vb + 8);
            ulonglong2 vc = *(const ulonglong2*)(vb + 12);
            fma2(acc0, P, va.x); fma2(acc1, P, va.y); fma2(acc2, P, vc.x); fma2(acc3, P, vc.y);
        }
        {
            unsigned long long P = pk2(p2, p2);
            ulonglong2 va = *(const ulonglong2*)(vb + 16);
            ulonglong2 vc = *(const ulonglong2*)(vb + 20);
            fma2(acc0, P, va.x); fma2(acc1, P, va.y); fma2(acc2, P, vc.x); fma2(acc3, P, vc.y);
        }
        {
            unsigned long long P = pk2(p3, p3);
            ulonglong2 va = *(const ulonglong2*)(vb + 24);
            ulonglong2 vc = *(const ulonglong2*)(vb + 28);
            fma2(acc0, P, va.x); fma2(acc1, P, va.y); fma2(acc2, P, vc.x); fma2(acc3, P, vc.y);
        }
    }
    for (int k = nquad << 2; k < n; k++) {
        float s = -m + fmaf(qs0, sKt[0][k], fmaf(qs1, sKt[1][k], fmaf(qs2, sKt[2][k], qs3 * sKt[3][k])));
        float p = ex2(s);
        denom += p;
        unsigned long long P = pk2(p, p);
        const float* vb = &sV[k * 8];
        ulonglong2 va = *(const ulonglong2*)(vb);
        ulonglong2 vc = *(const ulonglong2*)(vb + 4);
        fma2(acc0, P, va.x); fma2(acc1, P, va.y); fma2(acc2, P, vc.x); fma2(acc3, P, vc.y);
    }

    {
        float pm = ex2(-m);
        denom += (float)(SEQ - 1 - q) * pm;
        unsigned long long P = pk2(pm, pm);
        fma2(acc0, P, pk2(suf[0], suf[1]));
        fma2(acc1, P, pk2(suf[2], suf[3]));
        fma2(acc2, P, pk2(suf[4], suf[5]));
        fma2(acc3, P, pk2(suf[6], suf[7]));
    }

    const float inv = 1.0f / denom;
    float2 o0 = up2(acc0), o1 = up2(acc1), o2 = up2(acc2), o3 = up2(acc3);
    float vals[8] = {o0.x * inv, o0.y * inv, o1.x * inv, o1.y * inv,
                     o2.x * inv, o2.y * inv, o3.x * inv, o3.y * inv};

    __align__(16) __nv_bfloat16 H[8], M[8], L[8];
#pragma unroll
    for (int d = 0; d < 8; d++) split3(vals[d], H[d], M[d], L[d]);
    __nv_bfloat16* ob = OutS + (size_t)rowbase * KEXT + h * 8;
    *(uint4*)(ob)        = *(uint4*)H;
    *(uint4*)(ob + 512)  = *(uint4*)H;
    *(uint4*)(ob + 1024) = *(uint4*)M;
    *(uint4*)(ob + 1536) = *(uint4*)H;
    *(uint4*)(ob + 2048) = *(uint4*)L;
    *(uint4*)(ob + 2560) = *(uint4*)M;
}

// ---------------- NON-CAUSAL attention: 2 queries/thread, online softmax ----------------
__global__ __launch_bounds__(256, 2) void attnX_k(
    const float* __restrict__ Qa, const float* __restrict__ Qb,
    const float* __restrict__ KVbuf, float* __restrict__ Out)
{
    __shared__ float sKt[4][512];                 // K transposed: [dim][key]
    __shared__ __align__(16) float sV[512 * 8];   // V row-major:  [key][dim]

    const int bh = blockIdx.x;
    const int h = bh & 63, b = bh >> 6;
    const int t = threadIdx.x;

#pragma unroll
    for (int rr = 0; rr < 2; rr++) {
        const int row = t + rr * 256;
        const float* kv = KVbuf + (size_t)(b * SEQ + row) * 768;
        float4 kk = *(const float4*)(kv + h * 4);
        sKt[0][row] = kk.x; sKt[1][row] = kk.y; sKt[2][row] = kk.z; sKt[3][row] = kk.w;
        float4 v0 = *(const float4*)(kv + 256 + h * 8);
        float4 v1 = *(const float4*)(kv + 256 + h * 8 + 4);
        *(float4*)&sV[row * 8] = v0;
        *(float4*)&sV[row * 8 + 4] = v1;
    }
    __syncthreads();

    const float SCQ = 0.72134752044448170f;  // 0.5 * log2(e)
    unsigned long long aq1[4], aq2[4];
#pragma unroll
    for (int rr = 0; rr < 2; rr++) {
        const size_t row = (size_t)(b * SEQ + t + rr * 256);
        float4 qv = *(const float4*)(Qa + row * 256 + h * 4);
        float4 q2v = *(const float4*)(Qb + row * 256 + h * 4);
        qv.x += q2v.x; qv.y += q2v.y; qv.z += q2v.z; qv.w += q2v.w;
        unsigned long long* aq = rr ? aq2 : aq1;
        aq[0] = pk2(qv.x * SCQ, qv.x * SCQ);
        aq[1] = pk2(qv.y * SCQ, qv.y * SCQ);
        aq[2] = pk2(qv.z * SCQ, qv.z * SCQ);
        aq[3] = pk2(qv.w * SCQ, qv.w * SCQ);
    }

    float m1 = -1e30f, m2 = -1e30f;
    float d1 = 0.f, d2 = 0.f;
    unsigned long long A1[4] = {0ULL, 0ULL, 0ULL, 0ULL};
    unsigned long long A2[4] = {0ULL, 0ULL, 0ULL, 0ULL};

    auto step = [&](const float* s, float& m, float& dn, unsigned long long* A,
                    const ulonglong2* vv) {
        float qm = fmaxf(fmaxf(s[0], s[1]), fmaxf(s[2], s[3]));
        if (qm > m) {
            float r = ex2(m - qm);
            m = qm; dn *= r;
            unsigned long long R = pk2(r, r);
            mul2(A[0], R); mul2(A[1], R); mul2(A[2], R); mul2(A[3], R);
        }
        float p0 = ex2(s[0] - m), p1 = ex2(s[1] - m);
        float p2 = ex2(s[2] - m), p3 = ex2(s[3] - m);
        dn += (p0 + p1) + (p2 + p3);
        unsigned long long P;
        P = pk2(p0, p0);
        fma2(A[0], P, vv[0].x); fma2(A[1], P, vv[0].y); fma2(A[2], P, vv[1].x); fma2(A[3], P, vv[1].y);
        P = pk2(p1, p1);
        fma2(A[0], P, vv[2].x); fma2(A[1], P, vv[2].y); fma2(A[2], P, vv[3].x); fma2(A[3], P, vv[3].y);
        P = pk2(p2, p2);
        fma2(A[0], P, vv[4].x); fma2(A[1], P, vv[4].y); fma2(A[2], P, vv[5].x); fma2(A[3], P, vv[5].y);
        P = pk2(p3, p3);
        fma2(A[0], P, vv[6].x); fma2(A[1], P, vv[6].y); fma2(A[2], P, vv[7].x); fma2(A[3], P, vv[7].y);
    };

    for (int i = 0; i < 128; i++) {
        const int k4 = i << 2;
        ulonglong2 kq[4], vv[8];
        kq[0] = *(const ulonglong2*)&sKt[0][k4];
        kq[1] = *(const ulonglong2*)&sKt[1][k4];
        kq[2] = *(const ulonglong2*)&sKt[2][k4];
        kq[3] = *(const ulonglong2*)&sKt[3][k4];
        const float* vb = &sV[k4 * 8];
#pragma unroll
        for (int j = 0; j < 4; j++) {
            vv[2 * j]     = *(const ulonglong2*)(vb + j * 8);
            vv[2 * j + 1] = *(const ulonglong2*)(vb + j * 8 + 4);
        }
        float s1[4], s2[4];
        {
            unsigned long long s01 = 0ULL, s23 = 0ULL;
            fma2(s01, aq1[0], kq[0].x); fma2(s23, aq1[0], kq[0].y);
            fma2(s01, aq1[1], kq[1].x); fma2(s23, aq1[1], kq[1].y);
            fma2(s01, aq1[2], kq[2].x); fma2(s23, aq1[2], kq[2].y);
            fma2(s01, aq1[3], kq[3].x); fma2(s23, aq1[3], kq[3].y);
            float2 f01 = up2(s01), f23 = up2(s23);
            s1[0] = f01.x; s1[1] = f01.y; s1[2] = f23.x; s1[3] = f23.y;
        }
        {
            unsigned long long s01 = 0ULL, s23 = 0ULL;
            fma2(s01, aq2[0], kq[0].x); fma2(s23, aq2[0], kq[0].y);
            fma2(s01, aq2[1], kq[1].x); fma2(s23, aq2[1], kq[1].y);
            fma2(s01, aq2[2], kq[2].x); fma2(s23, aq2[2], kq[2].y);
            fma2(s01, aq2[3], kq[3].x); fma2(s23, aq2[3], kq[3].y);
            float2 f01 = up2(s01), f23 = up2(s23);
            s2[0] = f01.x; s2[1] = f01.y; s2[2] = f23.x; s2[3] = f23.y;
        }
        step(s1, m1, d1, A1, vv);
        step(s2, m2, d2, A2, vv);
    }

#pragma unroll
    for (int rr = 0; rr < 2; rr++) {
        const unsigned long long* A = rr ? A2 : A1;
        const float inv = 1.0f / (rr ? d2 : d1);
        float2 o0 = up2(A[0]), o1 = up2(A[1]), o2 = up2(A[2]), o3 = up2(A[3]);
        float* o = Out + (size_t)(b * SEQ + t + rr * 256) * DM + h * 8;
        *(float4*)(o)     = make_float4(o0.x * inv, o0.y * inv, o1.x * inv, o1.y * inv);
        *(float4*)(o + 4) = make_float4(o2.x * inv, o2.y * inv, o3.x * inv, o3.y * inv);
    }
}

// ---------------- Residual + LayerNorm + FFN (hidden=10) fused ----------------
#define HIDD 10
__global__ __launch_bounds__(256) void lnffn_k(
    const float* __restrict__ x, const float* __restrict__ fx,
    const float* __restrict__ lg, const float* __restrict__ lb,
    const float* __restrict__ w1, const float* __restrict__ b1,
    const float* __restrict__ w2, const float* __restrict__ b2,
    float* __restrict__ out)
{
    const int row = blockIdx.x;
    const int t = threadIdx.x;
    const int warp = t >> 5, lane = t & 31;

    const float* xr = x + row * DM;
    const float* fr = fx + row * DM;
    float v0 = xr[t] + fr[t];
    float v1 = xr[t + 256] + fr[t + 256];

    float s = v0 + v1;
    float ss = v0 * v0 + v1 * v1;
#pragma unroll
    for (int o = 16; o > 0; o >>= 1) {
        s  += __shfl_down_sync(0xffffffffu, s,  o);
        ss += __shfl_down_sync(0xffffffffu, ss, o);
    }
    __shared__ float rs[8], rss[8];
    if (lane == 0) { rs[warp] = s; rss[warp] = ss; }
    __syncthreads();
    float S = 0.f, SS = 0.f;
#pragma unroll
    for (int w = 0; w < 8; w++) { S += rs[w]; SS += rss[w]; }
    const float mu = S * (1.0f / DM);
    const float var = SS * (1.0f / DM) - mu * mu;
    const float rstd = rsqrtf(var + 1e-5f);

    const float y0 = (v0 - mu) * rstd * lg[t] + lb[t];
    const float y1 = (v1 - mu) * rstd * lg[t + 256] + lb[t + 256];

    float pj[HIDD];
#pragma unroll
    for (int j = 0; j < HIDD; j++)
        pj[j] = y0 * __ldg(&w1[j * DM + t]) + y1 * __ldg(&w1[j * DM + t + 256]);
#pragma unroll
    for (int j = 0; j < HIDD; j++)
#pragma unroll
        for (int o = 16; o > 0; o >>= 1)
            pj[j] += __shfl_down_sync(0xffffffffu, pj[j], o);

    __shared__ float hred[8][HIDD];
    if (lane == 0)
#pragma unroll
        for (int j = 0; j < HIDD; j++) hred[warp][j] = pj[j];
    __syncthreads();

    __shared__ float sh[HIDD];
    if (t < HIDD) {
        float hv = b1[t];
#pragma unroll
        for (int w = 0; w < 8; w++) hv += hred[w][t];
        sh[t] = fmaxf(hv, 0.f);
    }
    __syncthreads();

    float o0 = b2[t], o1 = b2[t + 256];
#pragma unroll
    for (int j = 0; j < HIDD; j++) {
        const float hj = sh[j];
        o0 = fmaf(hj, __ldg(&w2[t * HIDD + j]), o0);
        o1 = fmaf(hj, __ldg(&w2[(t + 256) * HIDD + j]), o1);
    }
    out[row * DM + t] = o0;
    out[row * DM + t + 256] = o1;
}

// ---------------- launch ----------------
extern "C" void kernel_launch(void* const* d_in, const int* in_sizes, int n_in,
                              void* d_out, int out_size)
{
    const float* x   = (const float*)d_in[0];
    const float* xe  = (const float*)d_in[1];
    const float* Wq  = (const float*)d_in[2];
    const float* Wk  = (const float*)d_in[3];
    const float* Wv  = (const float*)d_in[4];
    const float* lg  = (const float*)d_in[5];
    const float* lb  = (const float*)d_in[6];
    const float* w1  = (const float*)d_in[7];
    const float* b1  = (const float*)d_in[8];
    const float* w2  = (const float*)d_in[9];
    const float* b2  = (const float*)d_in[10];
    float* out = (float*)d_out;

    float *qkv, *kvenc, *q2a, *q2b, *fx2;
    __nv_bfloat16 *xs, *xes, *fxs, *ball;
    cudaGetSymbolAddress((void**)&qkv,   g_qkv);
    cudaGetSymbolAddress((void**)&kvenc, g_kvenc);
    cudaGetSymbolAddress((void**)&q2a,   g_q2a);
    cudaGetSymbolAddress((void**)&q2b,   g_q2b);
    cudaGetSymbolAddress((void**)&fx2,   g_fx2);
    cudaGetSymbolAddress((void**)&xs,    g_xs);
    cudaGetSymbolAddress((void**)&xes,   g_xes);
    cudaGetSymbolAddress((void**)&fxs,   g_fxs);
    cudaGetSymbolAddress((void**)&ball,  g_ball);

    cudaFuncSetAttribute(proj_k,   cudaFuncAttributeMaxDynamicSharedMemorySize, SMEM_MM);
    cudaFuncSetAttribute(crossq_k, cudaFuncAttributeMaxDynamicSharedMemorySize, SMEM_MM);

    // split inputs + weights into 6-segment bf16 K-extension
    splitAB_k<<<16384, 256>>>(x, xe, xs, xes);
    splitW_k<<<dim3(16, 56), dim3(32, 8)>>>(Wq, Wk, Wv, ball);

    // fused projections (KC64 + ldmatrix; best-measured GEMM)
    proj_k<<<448, 256, SMEM_MM>>>(xs, xes, ball, qkv, kvenc);

    // self-attention (1q/thread, 2-pass; best-measured); writes split-extended fxs
    attnC_k<<<512, 512>>>(qkv, fxs);

    // cross-attention Q projection (split-K=2 over segment halves)
    crossq_k<<<128, 256, SMEM_MM>>>(fxs, ball, q2a, q2b);

    // cross-attention (2q/thread online; best-measured), Q = q2a + q2b
    attnX_k<<<512, 256>>>(q2a, q2b, kvenc, fx2);

    // residual + LN + FFN
    lnffn_k<<<4096, 256>>>(x, fx2, lg, lb, w1, b1, w2, b2, out);
}

// round 14
// speedup vs baseline: 1.1752x; 1.0507x over previous
#include <cuda_runtime.h>
#include <cuda_bf16.h>
#include <cstdint>

#define BS 8
#define SEQ 512
#define DM 512
#define NROW (BS*SEQ)          // 4096
#define KEXT 3072              // 6 segments x 512
#define KC 64                  // GEMM k-chunk

// ---------------- scratch (no allocation allowed) ----------------
__device__ __align__(16) float g_qkv[NROW * 1024];    // [Q(256)|K(256)|V(512)] self
__device__ __align__(16) float g_kvenc[NROW * 768];   // [K(256)|V(512)] encoder
__device__ __align__(16) float g_q2a[NROW * 256];     // cross-Q split-K partial 0
__device__ __align__(16) float g_q2b[NROW * 256];     // cross-Q split-K partial 1
__device__ __align__(16) float g_fx2[NROW * 512];     // cross-attn output
__device__ __align__(16) __nv_bfloat16 g_xs [NROW * KEXT];   // x   split-extended
__device__ __align__(16) __nv_bfloat16 g_xes[NROW * KEXT];   // xe  split-extended
__device__ __align__(16) __nv_bfloat16 g_fxs[NROW * KEXT];   // fx  split-extended
__device__ __align__(16) __nv_bfloat16 g_ball[1792 * KEXT];  // [Wq|Wk|Wv|Wk|Wv]^T split

// ---------------- helpers ----------------
__device__ __forceinline__ uint32_t smem_u32(const void* p) {
    uint32_t a;
    asm("{ .reg .u64 t; cvta.to.shared.u64 t, %1; cvt.u32.u64 %0, t; }" : "=r"(a) : "l"(p));
    return a;
}
__device__ __forceinline__ float ex2(float x) {
    float y; asm("ex2.approx.f32 %0, %1;" : "=f"(y) : "f"(x)); return y;
}
__device__ __forceinline__ unsigned long long pk2(float x, float y) {
    unsigned long long r; asm("mov.b64 %0, {%1,%2};" : "=l"(r) : "f"(x), "f"(y)); return r;
}
__device__ __forceinline__ void fma2(unsigned long long& d, unsigned long long a, unsigned long long b) {
    asm("fma.rn.f32x2 %0, %1, %2, %0;" : "+l"(d) : "l"(a), "l"(b));
}
__device__ __forceinline__ void mul2(unsigned long long& d, unsigned long long a) {
    asm("mul.rn.f32x2 %0, %0, %1;" : "+l"(d) : "l"(a));
}
__device__ __forceinline__ float2 up2(unsigned long long v) {
    float2 r; asm("mov.b64 {%0,%1}, %2;" : "=f"(r.x), "=f"(r.y) : "l"(v)); return r;
}
__device__ __forceinline__ void cpasync16(uint32_t dst, const void* src) {
    asm volatile("cp.async.cg.shared.global [%0], [%1], 16;" :: "r"(dst), "l"(src));
}
__device__ __forceinline__ void ldsm4(uint32_t& r0, uint32_t& r1, uint32_t& r2, uint32_t& r3, uint32_t addr) {
    asm volatile("ldmatrix.sync.aligned.m8n8.x4.shared.b16 {%0,%1,%2,%3}, [%4];"
                 : "=r"(r0), "=r"(r1), "=r"(r2), "=r"(r3) : "r"(addr));
}

__device__ __forceinline__ void split3(float v, __nv_bfloat16& h, __nv_bfloat16& m, __nv_bfloat16& l) {
    h = __float2bfloat16(v);
    float r1 = v - __bfloat162float(h);
    m = __float2bfloat16(r1);
    float r2 = r1 - __bfloat162float(m);
    l = __float2bfloat16(r2);
}

// ---------------- split kernels ----------------
// A segments: [hi, hi, mid, hi, lo, mid]; handles x and xe in one launch.
__global__ __launch_bounds__(256) void splitAB_k(const float* __restrict__ x, const float* __restrict__ xe,
                                                 __nv_bfloat16* __restrict__ xs, __nv_bfloat16* __restrict__ xes)
{
    int gid = blockIdx.x * 256 + threadIdx.x;   // 2 * NROW*512
    const float* in; __nv_bfloat16* out; int id;
    if (gid < NROW * 512) { in = x; out = xs; id = gid; }
    else { in = xe; out = xes; id = gid - NROW * 512; }
    int r = id >> 9, c = id & 511;
    __nv_bfloat16 h, m, l;
    split3(in[id], h, m, l);
    __nv_bfloat16* o = out + (size_t)r * KEXT + c;
    o[0] = h; o[512] = h; o[1024] = m; o[1536] = h; o[2048] = l; o[2560] = m;
}

// B rows: g_ball[n][k] = W[k][n], segments [hi, mid, hi, lo, hi, mid]
__global__ void splitW_k(const float* __restrict__ Wq, const float* __restrict__ Wk,
                         const float* __restrict__ Wv, __nv_bfloat16* __restrict__ out)
{
    __shared__ float s[32][33];
    const int k0 = blockIdx.x * 32, n0 = blockIdx.y * 32;
    const int tx = threadIdx.x, ty = threadIdx.y;   // 32 x 8

    const float* src; int col0, ldw;
    if      (n0 < 256)  { src = Wq; col0 = n0;        ldw = 256; }
    else if (n0 < 512)  { src = Wk; col0 = n0 - 256;  ldw = 256; }
    else if (n0 < 1024) { src = Wv; col0 = n0 - 512;  ldw = 512; }
    else if (n0 < 1280) { src = Wk; col0 = n0 - 1024; ldw = 256; }
    else                { src = Wv; col0 = n0 - 1280; ldw = 512; }

#pragma unroll
    for (int i = 0; i < 4; i++) {
        int kk = ty + i * 8;
        s[kk][tx] = src[(k0 + kk) * ldw + col0 + tx];
    }
    __syncthreads();
#pragma unroll
    for (int i = 0; i < 4; i++) {
        int nn = ty + i * 8;
        __nv_bfloat16 h, m, l;
        split3(s[tx][nn], h, m, l);
        __nv_bfloat16* o = out + (size_t)(n0 + nn) * KEXT + k0 + tx;
        o[0] = h; o[512] = m; o[1024] = h; o[1536] = l; o[2048] = h; o[2560] = m;
    }
}

// ---------------- mma.sync GEMM body: 128x128 CTA tile, KC=64, ldmatrix ----------------
#define ROWB 144                     // 72 bf16 per row (64 + 8 pad), bytes
#define STAGE_B (128 * ROWB)         // bytes per stage per matrix
#define SMEM_MM (4 * STAGE_B)        // total dynamic smem (73728)

__device__ __forceinline__ void mma_body(char* smem,
    const __nv_bfloat16* __restrict__ A, const __nv_bfloat16* __restrict__ B,
    float* __restrict__ C, int ldc, int nch)
{
    const int tid = threadIdx.x;
    const int wid = tid >> 5, lane = tid & 31;

    const uint32_t sAb = smem_u32(smem);
    const uint32_t sBb = sAb + 2 * STAGE_B;

    auto issue = [&](int c, int buf) {
#pragma unroll
        for (int i = 0; i < 4; i++) {
            int g = tid + i * 256;           // 1024 granules of 16B
            int r = g >> 3, j = g & 7;
            uint32_t so = (uint32_t)buf * STAGE_B + r * ROWB + j * 16;
            cpasync16(sAb + so, (const char*)(A + (size_t)r * KEXT + c * KC + j * 8));
            cpasync16(sBb + so, (const char*)(B + (size_t)r * KEXT + c * KC + j * 8));
        }
    };

    issue(0, 0);
    asm volatile("cp.async.commit_group;" ::: "memory");
    issue(1, 1);
    asm volatile("cp.async.commit_group;" ::: "memory");

    float acc[4][4][4];
#pragma unroll
    for (int i = 0; i < 4; i++)
#pragma unroll
        for (int j = 0; j < 4; j++)
#pragma unroll
            for (int k = 0; k < 4; k++) acc[i][j][k] = 0.f;

    const int wm = wid >> 2, wn = wid & 3;
    const uint32_t lrow = lane & 15, lhalf = lane >> 4;
    const uint32_t aoff = (wm * 64 + lrow) * ROWB + lhalf * 16;
    const uint32_t boff = (wn * 32 + lrow) * ROWB + lhalf * 16;

    for (int c = 0; c < nch; c++) {
        asm volatile("cp.async.wait_group 1;" ::: "memory");
        __syncthreads();
        const uint32_t sa = sAb + (uint32_t)(c & 1) * STAGE_B + aoff;
        const uint32_t sb = sBb + (uint32_t)(c & 1) * STAGE_B + boff;

#pragma unroll
        for (int ks = 0; ks < 4; ks++) {
            uint32_t af[4][4], bf[4][2];
#pragma unroll
            for (int am = 0; am < 4; am++)
                ldsm4(af[am][0], af[am][1], af[am][2], af[am][3],
                      sa + am * 16 * ROWB + ks * 32);
#pragma unroll
            for (int anp = 0; anp < 2; anp++) {
                uint32_t r0, r1, r2, r3;
                ldsm4(r0, r1, r2, r3, sb + anp * 16 * ROWB + ks * 32);
                bf[2 * anp][0] = r0; bf[2 * anp + 1][0] = r1;
                bf[2 * anp][1] = r2; bf[2 * anp + 1][1] = r3;
            }
#pragma unroll
            for (int am = 0; am < 4; am++)
#pragma unroll
                for (int an = 0; an < 4; an++) {
                    asm volatile(
                        "mma.sync.aligned.m16n8k16.row.col.f32.bf16.bf16.f32 "
                        "{%0,%1,%2,%3}, {%4,%5,%6,%7}, {%8,%9}, {%0,%1,%2,%3};"
                        : "+f"(acc[am][an][0]), "+f"(acc[am][an][1]),
                          "+f"(acc[am][an][2]), "+f"(acc[am][an][3])
                        : "r"(af[am][0]), "r"(af[am][1]), "r"(af[am][2]), "r"(af[am][3]),
                          "r"(bf[an][0]), "r"(bf[an][1]));
                }
        }
        __syncthreads();
        if (c + 2 < nch) issue(c + 2, c & 1);
        asm volatile("cp.async.commit_group;" ::: "memory");
    }

#pragma unroll
    for (int am = 0; am < 4; am++) {
#pragma unroll
        for (int an = 0; an < 4; an++) {
            int r0 = wm * 64 + am * 16 + (lane >> 2);
            int cc = wn * 32 + an * 8 + (lane & 3) * 2;
            *(float2*)&C[r0 * ldc + cc]       = make_float2(acc[am][an][0], acc[am][an][1]);
            *(float2*)&C[(r0 + 8) * ldc + cc] = make_float2(acc[am][an][2], acc[am][an][3]);
        }
    }
}

// fused projections, 448 blocks, heavy (6-limb) first, light (3-limb enc-V) last
__global__ __launch_bounds__(256, 2) void proj_k(
    const __nv_bfloat16* __restrict__ xs, const __nv_bfloat16* __restrict__ xes,
    const __nv_bfloat16* __restrict__ ball, float* __restrict__ qkv, float* __restrict__ kvenc)
{
    extern __shared__ char smem[];
    const int bid = blockIdx.x;
    const __nv_bfloat16 *A, *B; float* C; int ldc, nch, bx, by;
    if (bid < 256) {
        bx = bid & 7; by = bid >> 3;
        A = xs; B = ball; C = qkv; ldc = 1024; nch = 48;
    } else if (bid < 320) {
        int i = bid - 256; bx = i & 1; by = i >> 1;
        A = xes; B = ball + (size_t)1024 * KEXT; C = kvenc; ldc = 768; nch = 48;
    } else {
        int i = bid - 320; bx = 2 + (i & 3); by = i >> 2;
        A = xes; B = ball + (size_t)1024 * KEXT; C = kvenc; ldc = 768; nch = 24;
    }
    mma_body(smem, A + (size_t)by * 128 * KEXT, B + (size_t)bx * 128 * KEXT,
             C + (size_t)by * 128 * ldc + bx * 128, ldc, nch);
}

// cross-Q GEMM: split-K=2 over the 6 segments: half0 = [h,h,m], half1 = [h,l,m]
__global__ __launch_bounds__(256, 2) void crossq_k(
    const __nv_bfloat16* __restrict__ fxs, const __nv_bfloat16* __restrict__ ball,
    float* __restrict__ q2a, float* __restrict__ q2b)
{
    extern __shared__ char smem[];
    const int bid = blockIdx.x;            // 128
    const int half = bid >> 6;
    const int i = bid & 63;
    const int bx = i & 1, by = i >> 1;
    const __nv_bfloat16* A = fxs + half * 1536;
    const __nv_bfloat16* B = ball + half * 1536;
    float* C = half ? q2b : q2a;
    mma_body(smem, A + (size_t)by * 128 * KEXT, B + (size_t)bx * 128 * KEXT,
             C + (size_t)by * 128 * 256 + bx * 128, 256, 24);
}

// ---------------- CAUSAL attention: 1 query/thread, SINGLE-PASS online softmax ----------------
// Removes the max-pass entirely (LDS/quad 16 -> 12). m init 0 (masked-zero quirk);
// rare monotone rescale keeps math shift-exact. Masked V tail via warp-scan suffix sums.
__global__ __launch_bounds__(512, 2) void attnC_k(
    const float* __restrict__ QKV, __nv_bfloat16* __restrict__ OutS)
{
    __shared__ float sKt[4][512];                 // K transposed: [dim][key]
    __shared__ __align__(16) float sV[512 * 8];   // V row-major:  [key][dim]
    __shared__ float sWS[16][8];                  // warp V-sums for suffix scan

    const int bh = blockIdx.x;
    const int h = bh & 63, b = bh >> 6;
    const int t = threadIdx.x, lane = t & 31, wid = t >> 5;
    const int rowbase = b * SEQ + t;

    const float* kv = QKV + (size_t)rowbase * 1024;
    float4 kk = *(const float4*)(kv + 256 + h * 4);
    sKt[0][t] = kk.x; sKt[1][t] = kk.y; sKt[2][t] = kk.z; sKt[3][t] = kk.w;
    float4 v0 = *(const float4*)(kv + 512 + h * 8);
    float4 v1 = *(const float4*)(kv + 512 + h * 8 + 4);
    *(float4*)&sV[t * 8] = v0;
    *(float4*)&sV[t * 8 + 4] = v1;

    float suf[8];
    {
        float vown[8] = {v0.x, v0.y, v0.z, v0.w, v1.x, v1.y, v1.z, v1.w};
#pragma unroll
        for (int d = 0; d < 8; d++) suf[d] = vown[d];
#pragma unroll
        for (int off = 1; off < 32; off <<= 1) {
#pragma unroll
            for (int d = 0; d < 8; d++) {
                float o = __shfl_down_sync(0xffffffffu, suf[d], off);
                if (lane + off < 32) suf[d] += o;
            }
        }
        if (lane == 0) {
#pragma unroll
            for (int d = 0; d < 8; d++) sWS[wid][d] = suf[d];
        }
        __syncthreads();
        for (int w = wid + 1; w < 16; w++)
#pragma unroll
            for (int d = 0; d < 8; d++) suf[d] += sWS[w][d];
#pragma unroll
        for (int d = 0; d < 8; d++) suf[d] -= vown[d];   // sum_{k > t}
    }

    const int q = t;
    const float SCQ = 0.72134752044448170f;  // 0.5 * log2(e)
    float4 qv = *(const float4*)(QKV + (size_t)rowbase * 1024 + h * 4);
    const float qs0 = qv.x * SCQ, qs1 = qv.y * SCQ, qs2 = qv.z * SCQ, qs3 = qv.w * SCQ;
    unsigned long long aq0 = pk2(qs0, qs0), aq1 = pk2(qs1, qs1);
    unsigned long long aq2 = pk2(qs2, qs2), aq3 = pk2(qs3, qs3);

    const int n = q + 1;
    const int nquad = n >> 2;

    float m = 0.f;        // masked zeros participate in softmax
    float denom = 0.f;
    unsigned long long acc0 = 0, acc1 = 0, acc2 = 0, acc3 = 0;

    for (int i = 0; i < nquad; i++) {
        const int k4 = i << 2;
        ulonglong2 k0 = *(const ulonglong2*)&sKt[0][k4];
        ulonglong2 k1 = *(const ulonglong2*)&sKt[1][k4];
        ulonglong2 k2 = *(const ulonglong2*)&sKt[2][k4];
        ulonglong2 k3 = *(const ulonglong2*)&sKt[3][k4];
        unsigned long long s01 = 0ULL, s23 = 0ULL;
        fma2(s01, aq0, k0.x); fma2(s23, aq0, k0.y);
        fma2(s01, aq1, k1.x); fma2(s23, aq1, k1.y);
        fma2(s01, aq2, k2.x); fma2(s23, aq2, k2.y);
        fma2(s01, aq3, k3.x); fma2(s23, aq3, k3.y);
        float2 f01 = up2(s01), f23 = up2(s23);

        float qm = fmaxf(fmaxf(f01.x, f01.y), fmaxf(f23.x, f23.y));
        if (qm > m) {
            float r = ex2(m - qm);
            m = qm; denom *= r;
            unsigned long long R = pk2(r, r);
            mul2(acc0, R); mul2(acc1, R); mul2(acc2, R); mul2(acc3, R);
        }
        float p0 = ex2(f01.x - m), p1 = ex2(f01.y - m);
        float p2 = ex2(f23.x - m), p3 = ex2(f23.y - m);
        denom += (p0 + p1) + (p2 + p3);

        const float* vb = &sV[k4 * 8];
        {
            unsigned long long P = pk2(p0, p0);
            ulonglong2 va = *(const ulonglong2*)(vb);
            ulonglong2 vc = *(const ulonglong2*)(vb + 4);
            fma2(acc0, P, va.x); fma2(acc1, P, va.y); fma2(acc2, P, vc.x); fma2(acc3, P, vc.y);
        }
        {
            unsigned long long P = pk2(p1, p1);
            ulonglong2 va = *(const ulonglong2*)(vb + 8);
            ulonglong2 vc = *(const ulonglong2*)(vb + 12);
            fma2(acc0, P, va.x); fma2(acc1, P, va.y); fma2(acc2, P, vc.x); fma2(acc3, P, vc.y);
        }
        {
            unsigned long long P = pk2(p2, p2);
            ulonglong2 va = *(const ulonglong2*)(vb + 16);
            ulonglong2 vc = *(const ulonglong2*)(vb + 20);
            fma2(acc0, P, va.x); fma2(acc1, P, va.y); fma2(acc2, P, vc.x); fma2(acc3, P, vc.y);
        }
        {
            unsigned long long P = pk2(p3, p3);
            ulonglong2 va = *(const ulonglong2*)(vb + 24);
            ulonglong2 vc = *(const ulonglong2*)(vb + 28);
            fma2(acc0, P, va.x); fma2(acc1, P, va.y); fma2(acc2, P, vc.x); fma2(acc3, P, vc.y);
        }
    }
    // scalar tail keys (nquad*4 .. q), online
    for (int k = nquad << 2; k < n; k++) {
        float s = fmaf(qs0, sKt[0][k], fmaf(qs1, sKt[1][k], fmaf(qs2, sKt[2][k], qs3 * sKt[3][k])));
        if (s > m) {
            float r = ex2(m - s);
            m = s; denom *= r;
            unsigned long long R = pk2(r, r);
            mul2(acc0, R); mul2(acc1, R); mul2(acc2, R); mul2(acc3, R);
        }
        float p = ex2(s - m);
        denom += p;
        unsigned long long P = pk2(p, p);
        const float* vb = &sV[k * 8];
        ulonglong2 va = *(const ulonglong2*)(vb);
        ulonglong2 vc = *(const ulonglong2*)(vb + 4);
        fma2(acc0, P, va.x); fma2(acc1, P, va.y); fma2(acc2, P, vc.x); fma2(acc3, P, vc.y);
    }

    // masked-zero tail: weight ex2(-m) per masked key, V via strict suffix sums
    {
        float pm = ex2(-m);
        denom += (float)(SEQ - 1 - q) * pm;
        unsigned long long P = pk2(pm, pm);
        fma2(acc0, P, pk2(suf[0], suf[1]));
        fma2(acc1, P, pk2(suf[2], suf[3]));
        fma2(acc2, P, pk2(suf[4], suf[5]));
        fma2(acc3, P, pk2(suf[6], suf[7]));
    }

    const float inv = 1.0f / denom;
    float2 o0 = up2(acc0), o1 = up2(acc1), o2 = up2(acc2), o3 = up2(acc3);
    float vals[8] = {o0.x * inv, o0.y * inv, o1.x * inv, o1.y * inv,
                     o2.x * inv, o2.y * inv, o3.x * inv, o3.y * inv};

    __align__(16) __nv_bfloat16 H[8], M[8], L[8];
#pragma unroll
    for (int d = 0; d < 8; d++) split3(vals[d], H[d], M[d], L[d]);
    __nv_bfloat16* ob = OutS + (size_t)rowbase * KEXT + h * 8;
    *(uint4*)(ob)        = *(uint4*)H;
    *(uint4*)(ob + 512)  = *(uint4*)H;
    *(uint4*)(ob + 1024) = *(uint4*)M;
    *(uint4*)(ob + 1536) = *(uint4*)H;
    *(uint4*)(ob + 2048) = *(uint4*)L;
    *(uint4*)(ob + 2560) = *(uint4*)M;
}

// ---------------- NON-CAUSAL attention: 2 queries/thread, online softmax ----------------
__global__ __launch_bounds__(256, 2) void attnX_k(
    const float* __restrict__ Qa, const float* __restrict__ Qb,
    const float* __restrict__ KVbuf, float* __restrict__ Out)
{
    __shared__ float sKt[4][512];                 // K transposed: [dim][key]
    __shared__ __align__(16) float sV[512 * 8];   // V row-major:  [key][dim]

    const int bh = blockIdx.x;
    const int h = bh & 63, b = bh >> 6;
    const int t = threadIdx.x;

#pragma unroll
    for (int rr = 0; rr < 2; rr++) {
        const int row = t + rr * 256;
        const float* kv = KVbuf + (size_t)(b * SEQ + row) * 768;
        float4 kk = *(const float4*)(kv + h * 4);
        sKt[0][row] = kk.x; sKt[1][row] = kk.y; sKt[2][row] = kk.z; sKt[3][row] = kk.w;
        float4 v0 = *(const float4*)(kv + 256 + h * 8);
        float4 v1 = *(const float4*)(kv + 256 + h * 8 + 4);
        *(float4*)&sV[row * 8] = v0;
        *(float4*)&sV[row * 8 + 4] = v1;
    }
    __syncthreads();

    const float SCQ = 0.72134752044448170f;  // 0.5 * log2(e)
    unsigned long long aq1[4], aq2[4];
#pragma unroll
    for (int rr = 0; rr < 2; rr++) {
        const size_t row = (size_t)(b * SEQ + t + rr * 256);
        float4 qv = *(const float4*)(Qa + row * 256 + h * 4);
        float4 q2v = *(const float4*)(Qb + row * 256 + h * 4);
        qv.x += q2v.x; qv.y += q2v.y; qv.z += q2v.z; qv.w += q2v.w;
        unsigned long long* aq = rr ? aq2 : aq1;
        aq[0] = pk2(qv.x * SCQ, qv.x * SCQ);
        aq[1] = pk2(qv.y * SCQ, qv.y * SCQ);
        aq[2] = pk2(qv.z * SCQ, qv.z * SCQ);
        aq[3] = pk2(qv.w * SCQ, qv.w * SCQ);
    }

    float m1 = -1e30f, m2 = -1e30f;
    float d1 = 0.f, d2 = 0.f;
    unsigned long long A1[4] = {0ULL, 0ULL, 0ULL, 0ULL};
    unsigned long long A2[4] = {0ULL, 0ULL, 0ULL, 0ULL};

    auto step = [&](const float* s, float& m, float& dn, unsigned long long* A,
                    const ulonglong2* vv) {
        float qm = fmaxf(fmaxf(s[0], s[1]), fmaxf(s[2], s[3]));
        if (qm > m) {
            float r = ex2(m - qm);
            m = qm; dn *= r;
            unsigned long long R = pk2(r, r);
            mul2(A[0], R); mul2(A[1], R); mul2(A[2], R); mul2(A[3], R);
        }
        float p0 = ex2(s[0] - m), p1 = ex2(s[1] - m);
        float p2 = ex2(s[2] - m), p3 = ex2(s[3] - m);
        dn += (p0 + p1) + (p2 + p3);
        unsigned long long P;
        P = pk2(p0, p0);
        fma2(A[0], P, vv[0].x); fma2(A[1], P, vv[0].y); fma2(A[2], P, vv[1].x); fma2(A[3], P, vv[1].y);
        P = pk2(p1, p1);
        fma2(A[0], P, vv[2].x); fma2(A[1], P, vv[2].y); fma2(A[2], P, vv[3].x); fma2(A[3], P, vv[3].y);
        P = pk2(p2, p2);
        fma2(A[0], P, vv[4].x); fma2(A[1], P, vv[4].y); fma2(A[2], P, vv[5].x); fma2(A[3], P, vv[5].y);
        P = pk2(p3, p3);
        fma2(A[0], P, vv[6].x); fma2(A[1], P, vv[6].y); fma2(A[2], P, vv[7].x); fma2(A[3], P, vv[7].y);
    };

    for (int i = 0; i < 128; i++) {
        const int k4 = i << 2;
        ulonglong2 kq[4], vv[8];
        kq[0] = *(const ulonglong2*)&sKt[0][k4];
        kq[1] = *(const ulonglong2*)&sKt[1][k4];
        kq[2] = *(const ulonglong2*)&sKt[2][k4];
        kq[3] = *(const ulonglong2*)&sKt[3][k4];
        const float* vb = &sV[k4 * 8];
#pragma unroll
        for (int j = 0; j < 4; j++) {
            vv[2 * j]     = *(const ulonglong2*)(vb + j * 8);
            vv[2 * j + 1] = *(const ulonglong2*)(vb + j * 8 + 4);
        }
        float s1[4], s2[4];
        {
            unsigned long long s01 = 0ULL, s23 = 0ULL;
            fma2(s01, aq1[0], kq[0].x); fma2(s23, aq1[0], kq[0].y);
            fma2(s01, aq1[1], kq[1].x); fma2(s23, aq1[1], kq[1].y);
            fma2(s01, aq1[2], kq[2].x); fma2(s23, aq1[2], kq[2].y);
            fma2(s01, aq1[3], kq[3].x); fma2(s23, aq1[3], kq[3].y);
            float2 f01 = up2(s01), f23 = up2(s23);
            s1[0] = f01.x; s1[1] = f01.y; s1[2] = f23.x; s1[3] = f23.y;
        }
        {
            unsigned long long s01 = 0ULL, s23 = 0ULL;
            fma2(s01, aq2[0], kq[0].x); fma2(s23, aq2[0], kq[0].y);
            fma2(s01, aq2[1], kq[1].x); fma2(s23, aq2[1], kq[1].y);
            fma2(s01, aq2[2], kq[2].x); fma2(s23, aq2[2], kq[2].y);
            fma2(s01, aq2[3], kq[3].x); fma2(s23, aq2[3], kq[3].y);
            float2 f01 = up2(s01), f23 = up2(s23);
            s2[0] = f01.x; s2[1] = f01.y; s2[2] = f23.x; s2[3] = f23.y;
        }
        step(s1, m1, d1, A1, vv);
        step(s2, m2, d2, A2, vv);
    }

#pragma unroll
    for (int rr = 0; rr < 2; rr++) {
        const unsigned long long* A = rr ? A2 : A1;
        const float inv = 1.0f / (rr ? d2 : d1);
        float2 o0 = up2(A[0]), o1 = up2(A[1]), o2 = up2(A[2]), o3 = up2(A[3]);
        float* o = Out + (size_t)(b * SEQ + t + rr * 256) * DM + h * 8;
        *(float4*)(o)     = make_float4(o0.x * inv, o0.y * inv, o1.x * inv, o1.y * inv);
        *(float4*)(o + 4) = make_float4(o2.x * inv, o2.y * inv, o3.x * inv, o3.y * inv);
    }
}

// ---------------- Residual + LayerNorm + FFN (hidden=10) fused ----------------
#define HIDD 10
__global__ __launch_bounds__(256) void lnffn_k(
    const float* __restrict__ x, const float* __restrict__ fx,
    const float* __restrict__ lg, const float* __restrict__ lb,
    const float* __restrict__ w1, const float* __restrict__ b1,
    const float* __restrict__ w2, const float* __restrict__ b2,
    float* __restrict__ out)
{
    const int row = blockIdx.x;
    const int t = threadIdx.x;
    const int warp = t >> 5, lane = t & 31;

    const float* xr = x + row * DM;
    const float* fr = fx + row * DM;
    float v0 = xr[t] + fr[t];
    float v1 = xr[t + 256] + fr[t + 256];

    float s = v0 + v1;
    float ss = v0 * v0 + v1 * v1;
#pragma unroll
    for (int o = 16; o > 0; o >>= 1) {
        s  += __shfl_down_sync(0xffffffffu, s,  o);
        ss += __shfl_down_sync(0xffffffffu, ss, o);
    }
    __shared__ float rs[8], rss[8];
    if (lane == 0) { rs[warp] = s; rss[warp] = ss; }
    __syncthreads();
    float S = 0.f, SS = 0.f;
#pragma unroll
    for (int w = 0; w < 8; w++) { S += rs[w]; SS += rss[w]; }
    const float mu = S * (1.0f / DM);
    const float var = SS * (1.0f / DM) - mu * mu;
    const float rstd = rsqrtf(var + 1e-5f);

    const float y0 = (v0 - mu) * rstd * lg[t] + lb[t];
    const float y1 = (v1 - mu) * rstd * lg[t + 256] + lb[t + 256];

    float pj[HIDD];
#pragma unroll
    for (int j = 0; j < HIDD; j++)
        pj[j] = y0 * __ldg(&w1[j * DM + t]) + y1 * __ldg(&w1[j * DM + t + 256]);
#pragma unroll
    for (int j = 0; j < HIDD; j++)
#pragma unroll
        for (int o = 16; o > 0; o >>= 1)
            pj[j] += __shfl_down_sync(0xffffffffu, pj[j], o);

    __shared__ float hred[8][HIDD];
    if (lane == 0)
#pragma unroll
        for (int j = 0; j < HIDD; j++) hred[warp][j] = pj[j];
    __syncthreads();

    __shared__ float sh[HIDD];
    if (t < HIDD) {
        float hv = b1[t];
#pragma unroll
        for (int w = 0; w < 8; w++) hv += hred[w][t];
        sh[t] = fmaxf(hv, 0.f);
    }
    __syncthreads();

    float o0 = b2[t], o1 = b2[t + 256];
#pragma unroll
    for (int j = 0; j < HIDD; j++) {
        const float hj = sh[j];
        o0 = fmaf(hj, __ldg(&w2[t * HIDD + j]), o0);
        o1 = fmaf(hj, __ldg(&w2[(t + 256) * HIDD + j]), o1);
    }
    out[row * DM + t] = o0;
    out[row * DM + t + 256] = o1;
}

// ---------------- launch ----------------
extern "C" void kernel_launch(void* const* d_in, const int* in_sizes, int n_in,
                              void* d_out, int out_size)
{
    const float* x   = (const float*)d_in[0];
    const float* xe  = (const float*)d_in[1];
    const float* Wq  = (const float*)d_in[2];
    const float* Wk  = (const float*)d_in[3];
    const float* Wv  = (const float*)d_in[4];
    const float* lg  = (const float*)d_in[5];
    const float* lb  = (const float*)d_in[6];
    const float* w1  = (const float*)d_in[7];
    const float* b1  = (const float*)d_in[8];
    const float* w2  = (const float*)d_in[9];
    const float* b2  = (const float*)d_in[10];
    float* out = (float*)d_out;

    float *qkv, *kvenc, *q2a, *q2b, *fx2;
    __nv_bfloat16 *xs, *xes, *fxs, *ball;
    cudaGetSymbolAddress((void**)&qkv,   g_qkv);
    cudaGetSymbolAddress((void**)&kvenc, g_kvenc);
    cudaGetSymbolAddress((void**)&q2a,   g_q2a);
    cudaGetSymbolAddress((void**)&q2b,   g_q2b);
    cudaGetSymbolAddress((void**)&fx2,   g_fx2);
    cudaGetSymbolAddress((void**)&xs,    g_xs);
    cudaGetSymbolAddress((void**)&xes,   g_xes);
    cudaGetSymbolAddress((void**)&fxs,   g_fxs);
    cudaGetSymbolAddress((void**)&ball,  g_ball);

    cudaFuncSetAttribute(proj_k,   cudaFuncAttributeMaxDynamicSharedMemorySize, SMEM_MM);
    cudaFuncSetAttribute(crossq_k, cudaFuncAttributeMaxDynamicSharedMemorySize, SMEM_MM);

    // split inputs + weights into 6-segment bf16 K-extension
    splitAB_k<<<16384, 256>>>(x, xe, xs, xes);
    splitW_k<<<dim3(16, 56), dim3(32, 8)>>>(Wq, Wk, Wv, ball);

    // fused projections (KC64 + ldmatrix; best-measured GEMM)
    proj_k<<<448, 256, SMEM_MM>>>(xs, xes, ball, qkv, kvenc);

    // self-attention (1q/thread, single-pass online); writes split-extended fxs
    attnC_k<<<512, 512>>>(qkv, fxs);

    // cross-attention Q projection (split-K=2 over segment halves)
    crossq_k<<<128, 256, SMEM_MM>>>(fxs, ball, q2a, q2b);

    // cross-attention (2q/thread online; best-measured), Q = q2a + q2b
    attnX_k<<<512, 256>>>(q2a, q2b, kvenc, fx2);

    // residual + LN + FFN
    lnffn_k<<<4096, 256>>>(x, fx2, lg, lb, w1, b1, w2, b2, out);
}

// round 15
// speedup vs baseline: 1.1859x; 1.0091x over previous
#include <cuda_runtime.h>
#include <cuda_bf16.h>
#include <cstdint>

#define BS 8
#define SEQ 512
#define DM 512
#define NROW (BS*SEQ)          // 4096
#define KEXT 3072              // 6 segments x 512
#define KC 64                  // GEMM k-chunk

// ---------------- scratch (no allocation allowed) ----------------
__device__ __align__(16) float g_qkv[NROW * 1024];    // [Q(256)|K(256)|V(512)] self
__device__ __align__(16) float g_kvenc[NROW * 768];   // [K(256)|V(512)] encoder
__device__ __align__(16) float g_q2a[NROW * 256];     // cross-Q split-K partial 0
__device__ __align__(16) float g_q2b[NROW * 256];     // cross-Q split-K partial 1
__device__ __align__(16) float g_fx2[NROW * 512];     // cross-attn output
__device__ __align__(16) __nv_bfloat16 g_xs [NROW * KEXT];   // x   split-extended
__device__ __align__(16) __nv_bfloat16 g_xes[NROW * KEXT];   // xe  split-extended
__device__ __align__(16) __nv_bfloat16 g_fxs[NROW * KEXT];   // fx  split-extended
__device__ __align__(16) __nv_bfloat16 g_ball[1792 * KEXT];  // [Wq|Wk|Wv|Wk|Wv]^T split

// ---------------- helpers ----------------
__device__ __forceinline__ uint32_t smem_u32(const void* p) {
    uint32_t a;
    asm("{ .reg .u64 t; cvta.to.shared.u64 t, %1; cvt.u32.u64 %0, t; }" : "=r"(a) : "l"(p));
    return a;
}
__device__ __forceinline__ float ex2(float x) {
    float y; asm("ex2.approx.f32 %0, %1;" : "=f"(y) : "f"(x)); return y;
}
__device__ __forceinline__ unsigned long long pk2(float x, float y) {
    unsigned long long r; asm("mov.b64 %0, {%1,%2};" : "=l"(r) : "f"(x), "f"(y)); return r;
}
__device__ __forceinline__ void fma2(unsigned long long& d, unsigned long long a, unsigned long long b) {
    asm("fma.rn.f32x2 %0, %1, %2, %0;" : "+l"(d) : "l"(a), "l"(b));
}
__device__ __forceinline__ void mul2(unsigned long long& d, unsigned long long a) {
    asm("mul.rn.f32x2 %0, %0, %1;" : "+l"(d) : "l"(a));
}
__device__ __forceinline__ void add2(unsigned long long& d, unsigned long long a) {
    asm("add.rn.f32x2 %0, %0, %1;" : "+l"(d) : "l"(a));
}
__device__ __forceinline__ float2 up2(unsigned long long v) {
    float2 r; asm("mov.b64 {%0,%1}, %2;" : "=f"(r.x), "=f"(r.y) : "l"(v)); return r;
}
__device__ __forceinline__ void cpasync16(uint32_t dst, const void* src) {
    asm volatile("cp.async.cg.shared.global [%0], [%1], 16;" :: "r"(dst), "l"(src));
}
__device__ __forceinline__ void ldsm4(uint32_t& r0, uint32_t& r1, uint32_t& r2, uint32_t& r3, uint32_t addr) {
    asm volatile("ldmatrix.sync.aligned.m8n8.x4.shared.b16 {%0,%1,%2,%3}, [%4];"
                 : "=r"(r0), "=r"(r1), "=r"(r2), "=r"(r3) : "r"(addr));
}

__device__ __forceinline__ void split3(float v, __nv_bfloat16& h, __nv_bfloat16& m, __nv_bfloat16& l) {
    h = __float2bfloat16(v);
    float r1 = v - __bfloat162float(h);
    m = __float2bfloat16(r1);
    float r2 = r1 - __bfloat162float(m);
    l = __float2bfloat16(r2);
}

// ---------------- split kernels ----------------
// A segments: [hi, hi, mid, hi, lo, mid]; handles x and xe in one launch.
__global__ __launch_bounds__(256) void splitAB_k(const float* __restrict__ x, const float* __restrict__ xe,
                                                 __nv_bfloat16* __restrict__ xs, __nv_bfloat16* __restrict__ xes)
{
    int gid = blockIdx.x * 256 + threadIdx.x;   // 2 * NROW*512
    const float* in; __nv_bfloat16* out; int id;
    if (gid < NROW * 512) { in = x; out = xs; id = gid; }
    else { in = xe; out = xes; id = gid - NROW * 512; }
    int r = id >> 9, c = id & 511;
    __nv_bfloat16 h, m, l;
    split3(in[id], h, m, l);
    __nv_bfloat16* o = out + (size_t)r * KEXT + c;
    o[0] = h; o[512] = h; o[1024] = m; o[1536] = h; o[2048] = l; o[2560] = m;
}

// B rows: g_ball[n][k] = W[k][n], segments [hi, mid, hi, lo, hi, mid]
__global__ void splitW_k(const float* __restrict__ Wq, const float* __restrict__ Wk,
                         const float* __restrict__ Wv, __nv_bfloat16* __restrict__ out)
{
    __shared__ float s[32][33];
    const int k0 = blockIdx.x * 32, n0 = blockIdx.y * 32;
    const int tx = threadIdx.x, ty = threadIdx.y;   // 32 x 8

    const float* src; int col0, ldw;
    if      (n0 < 256)  { src = Wq; col0 = n0;        ldw = 256; }
    else if (n0 < 512)  { src = Wk; col0 = n0 - 256;  ldw = 256; }
    else if (n0 < 1024) { src = Wv; col0 = n0 - 512;  ldw = 512; }
    else if (n0 < 1280) { src = Wk; col0 = n0 - 1024; ldw = 256; }
    else                { src = Wv; col0 = n0 - 1280; ldw = 512; }

#pragma unroll
    for (int i = 0; i < 4; i++) {
        int kk = ty + i * 8;
        s[kk][tx] = src[(k0 + kk) * ldw + col0 + tx];
    }
    __syncthreads();
#pragma unroll
    for (int i = 0; i < 4; i++) {
        int nn = ty + i * 8;
        __nv_bfloat16 h, m, l;
        split3(s[tx][nn], h, m, l);
        __nv_bfloat16* o = out + (size_t)(n0 + nn) * KEXT + k0 + tx;
        o[0] = h; o[512] = m; o[1024] = h; o[1536] = l; o[2048] = h; o[2560] = m;
    }
}

// ---------------- mma.sync GEMM body: 128x128 CTA tile, KC=64, ldmatrix ----------------
#define ROWB 144                     // 72 bf16 per row (64 + 8 pad), bytes
#define STAGE_B (128 * ROWB)         // bytes per stage per matrix
#define SMEM_MM (4 * STAGE_B)        // total dynamic smem (73728)

__device__ __forceinline__ void mma_body(char* smem,
    const __nv_bfloat16* __restrict__ A, const __nv_bfloat16* __restrict__ B,
    float* __restrict__ C, int ldc, int nch)
{
    const int tid = threadIdx.x;
    const int wid = tid >> 5, lane = tid & 31;

    const uint32_t sAb = smem_u32(smem);
    const uint32_t sBb = sAb + 2 * STAGE_B;

    auto issue = [&](int c, int buf) {
#pragma unroll
        for (int i = 0; i < 4; i++) {
            int g = tid + i * 256;           // 1024 granules of 16B
            int r = g >> 3, j = g & 7;
            uint32_t so = (uint32_t)buf * STAGE_B + r * ROWB + j * 16;
            cpasync16(sAb + so, (const char*)(A + (size_t)r * KEXT + c * KC + j * 8));
            cpasync16(sBb + so, (const char*)(B + (size_t)r * KEXT + c * KC + j * 8));
        }
    };

    issue(0, 0);
    asm volatile("cp.async.commit_group;" ::: "memory");
    issue(1, 1);
    asm volatile("cp.async.commit_group;" ::: "memory");

    float acc[4][4][4];
#pragma unroll
    for (int i = 0; i < 4; i++)
#pragma unroll
        for (int j = 0; j < 4; j++)
#pragma unroll
            for (int k = 0; k < 4; k++) acc[i][j][k] = 0.f;

    const int wm = wid >> 2, wn = wid & 3;
    const uint32_t lrow = lane & 15, lhalf = lane >> 4;
    const uint32_t aoff = (wm * 64 + lrow) * ROWB + lhalf * 16;
    const uint32_t boff = (wn * 32 + lrow) * ROWB + lhalf * 16;

    for (int c = 0; c < nch; c++) {
        asm volatile("cp.async.wait_group 1;" ::: "memory");
        __syncthreads();
        const uint32_t sa = sAb + (uint32_t)(c & 1) * STAGE_B + aoff;
        const uint32_t sb = sBb + (uint32_t)(c & 1) * STAGE_B + boff;

#pragma unroll
        for (int ks = 0; ks < 4; ks++) {
            uint32_t af[4][4], bf[4][2];
#pragma unroll
            for (int am = 0; am < 4; am++)
                ldsm4(af[am][0], af[am][1], af[am][2], af[am][3],
                      sa + am * 16 * ROWB + ks * 32);
#pragma unroll
            for (int anp = 0; anp < 2; anp++) {
                uint32_t r0, r1, r2, r3;
                ldsm4(r0, r1, r2, r3, sb + anp * 16 * ROWB + ks * 32);
                bf[2 * anp][0] = r0; bf[2 * anp + 1][0] = r1;
                bf[2 * anp][1] = r2; bf[2 * anp + 1][1] = r3;
            }
#pragma unroll
            for (int am = 0; am < 4; am++)
#pragma unroll
                for (int an = 0; an < 4; an++) {
                    asm volatile(
                        "mma.sync.aligned.m16n8k16.row.col.f32.bf16.bf16.f32 "
                        "{%0,%1,%2,%3}, {%4,%5,%6,%7}, {%8,%9}, {%0,%1,%2,%3};"
                        : "+f"(acc[am][an][0]), "+f"(acc[am][an][1]),
                          "+f"(acc[am][an][2]), "+f"(acc[am][an][3])
                        : "r"(af[am][0]), "r"(af[am][1]), "r"(af[am][2]), "r"(af[am][3]),
                          "r"(bf[an][0]), "r"(bf[an][1]));
                }
        }
        __syncthreads();
        if (c + 2 < nch) issue(c + 2, c & 1);
        asm volatile("cp.async.commit_group;" ::: "memory");
    }

#pragma unroll
    for (int am = 0; am < 4; am++) {
#pragma unroll
        for (int an = 0; an < 4; an++) {
            int r0 = wm * 64 + am * 16 + (lane >> 2);
            int cc = wn * 32 + an * 8 + (lane & 3) * 2;
            *(float2*)&C[r0 * ldc + cc]       = make_float2(acc[am][an][0], acc[am][an][1]);
            *(float2*)&C[(r0 + 8) * ldc + cc] = make_float2(acc[am][an][2], acc[am][an][3]);
        }
    }
}

// fused projections, 448 blocks, heavy (6-limb) first, light (3-limb enc-V) last
__global__ __launch_bounds__(256, 2) void proj_k(
    const __nv_bfloat16* __restrict__ xs, const __nv_bfloat16* __restrict__ xes,
    const __nv_bfloat16* __restrict__ ball, float* __restrict__ qkv, float* __restrict__ kvenc)
{
    extern __shared__ char smem[];
    const int bid = blockIdx.x;
    const __nv_bfloat16 *A, *B; float* C; int ldc, nch, bx, by;
    if (bid < 256) {
        bx = bid & 7; by = bid >> 3;
        A = xs; B = ball; C = qkv; ldc = 1024; nch = 48;
    } else if (bid < 320) {
        int i = bid - 256; bx = i & 1; by = i >> 1;
        A = xes; B = ball + (size_t)1024 * KEXT; C = kvenc; ldc = 768; nch = 48;
    } else {
        int i = bid - 320; bx = 2 + (i & 3); by = i >> 2;
        A = xes; B = ball + (size_t)1024 * KEXT; C = kvenc; ldc = 768; nch = 24;
    }
    mma_body(smem, A + (size_t)by * 128 * KEXT, B + (size_t)bx * 128 * KEXT,
             C + (size_t)by * 128 * ldc + bx * 128, ldc, nch);
}

// cross-Q GEMM: split-K=2 over the 6 segments: half0 = [h,h,m], half1 = [h,l,m]
__global__ __launch_bounds__(256, 2) void crossq_k(
    const __nv_bfloat16* __restrict__ fxs, const __nv_bfloat16* __restrict__ ball,
    float* __restrict__ q2a, float* __restrict__ q2b)
{
    extern __shared__ char smem[];
    const int bid = blockIdx.x;            // 128
    const int half = bid >> 6;
    const int i = bid & 63;
    const int bx = i & 1, by = i >> 1;
    const __nv_bfloat16* A = fxs + half * 1536;
    const __nv_bfloat16* B = ball + half * 1536;
    float* C = half ? q2b : q2a;
    mma_body(smem, A + (size_t)by * 128 * KEXT, B + (size_t)bx * 128 * KEXT,
             C + (size_t)by * 128 * 256 + bx * 128, 256, 24);
}

// ---------------- CAUSAL attention: 1 query/thread, single-pass online ----------------
// Dual accumulator sets (even/odd quads) break the serial fp32x2 accumulation
// chain; merged exactly at the end. m init 0 (masked-zero quirk); masked tail
// via warp-scan suffix sums.
__global__ __launch_bounds__(512, 2) void attnC_k(
    const float* __restrict__ QKV, __nv_bfloat16* __restrict__ OutS)
{
    __shared__ float sKt[4][512];                 // K transposed: [dim][key]
    __shared__ __align__(16) float sV[512 * 8];   // V row-major:  [key][dim]
    __shared__ float sWS[16][8];                  // warp V-sums for suffix scan

    const int bh = blockIdx.x;
    const int h = bh & 63, b = bh >> 6;
    const int t = threadIdx.x, lane = t & 31, wid = t >> 5;
    const int rowbase = b * SEQ + t;

    const float* kv = QKV + (size_t)rowbase * 1024;
    float4 kk = *(const float4*)(kv + 256 + h * 4);
    sKt[0][t] = kk.x; sKt[1][t] = kk.y; sKt[2][t] = kk.z; sKt[3][t] = kk.w;
    float4 v0 = *(const float4*)(kv + 512 + h * 8);
    float4 v1 = *(const float4*)(kv + 512 + h * 8 + 4);
    *(float4*)&sV[t * 8] = v0;
    *(float4*)&sV[t * 8 + 4] = v1;

    float suf[8];
    {
        float vown[8] = {v0.x, v0.y, v0.z, v0.w, v1.x, v1.y, v1.z, v1.w};
#pragma unroll
        for (int d = 0; d < 8; d++) suf[d] = vown[d];
#pragma unroll
        for (int off = 1; off < 32; off <<= 1) {
#pragma unroll
            for (int d = 0; d < 8; d++) {
                float o = __shfl_down_sync(0xffffffffu, suf[d], off);
                if (lane + off < 32) suf[d] += o;
            }
        }
        if (lane == 0) {
#pragma unroll
            for (int d = 0; d < 8; d++) sWS[wid][d] = suf[d];
        }
        __syncthreads();
        for (int w = wid + 1; w < 16; w++)
#pragma unroll
            for (int d = 0; d < 8; d++) suf[d] += sWS[w][d];
#pragma unroll
        for (int d = 0; d < 8; d++) suf[d] -= vown[d];   // sum_{k > t}
    }

    const int q = t;
    const float SCQ = 0.72134752044448170f;  // 0.5 * log2(e)
    float4 qv = *(const float4*)(QKV + (size_t)rowbase * 1024 + h * 4);
    const float qs0 = qv.x * SCQ, qs1 = qv.y * SCQ, qs2 = qv.z * SCQ, qs3 = qv.w * SCQ;
    unsigned long long aq0 = pk2(qs0, qs0), aq1 = pk2(qs1, qs1);
    unsigned long long aq2 = pk2(qs2, qs2), aq3 = pk2(qs3, qs3);

    const int n = q + 1;
    const int nquad = n >> 2;

    float m = 0.f;        // masked zeros participate in softmax
    float dA = 0.f, dB = 0.f;
    unsigned long long A0 = 0, A1 = 0, A2 = 0, A3 = 0;   // even-quad accs
    unsigned long long B0 = 0, B1 = 0, B2 = 0, B3 = 0;   // odd-quad accs

    // helper: score quad at k4 -> (f01, f23)
    auto scoreq = [&](int k4, float2& f01, float2& f23) {
        ulonglong2 k0 = *(const ulonglong2*)&sKt[0][k4];
        ulonglong2 k1 = *(const ulonglong2*)&sKt[1][k4];
        ulonglong2 k2 = *(const ulonglong2*)&sKt[2][k4];
        ulonglong2 k3 = *(const ulonglong2*)&sKt[3][k4];
        unsigned long long s01 = 0ULL, s23 = 0ULL;
        fma2(s01, aq0, k0.x); fma2(s23, aq0, k0.y);
        fma2(s01, aq1, k1.x); fma2(s23, aq1, k1.y);
        fma2(s01, aq2, k2.x); fma2(s23, aq2, k2.y);
        fma2(s01, aq3, k3.x); fma2(s23, aq3, k3.y);
        f01 = up2(s01); f23 = up2(s23);
    };
    // helper: weighted-V accumulate for quad k4 with probs p[4] into (X0..X3)
    auto vacc = [&](int k4, const float* p,
                    unsigned long long& X0, unsigned long long& X1,
                    unsigned long long& X2, unsigned long long& X3) {
        const float* vb = &sV[k4 * 8];
#pragma unroll
        for (int j = 0; j < 4; j++) {
            unsigned long long P = pk2(p[j], p[j]);
            ulonglong2 va = *(const ulonglong2*)(vb + j * 8);
            ulonglong2 vc = *(const ulonglong2*)(vb + j * 8 + 4);
            fma2(X0, P, va.x); fma2(X1, P, va.y); fma2(X2, P, vc.x); fma2(X3, P, vc.y);
        }
    };

    int i = 0;
    for (; i + 2 <= nquad; i += 2) {
        const int k4a = i << 2, k4b = k4a + 4;
        float2 fa01, fa23, fb01, fb23;
        scoreq(k4a, fa01, fa23);
        scoreq(k4b, fb01, fb23);
        float qm = fmaxf(fmaxf(fmaxf(fa01.x, fa01.y), fmaxf(fa23.x, fa23.y)),
                         fmaxf(fmaxf(fb01.x, fb01.y), fmaxf(fb23.x, fb23.y)));
        if (qm > m) {
            float r = ex2(m - qm);
            m = qm; dA *= r; dB *= r;
            unsigned long long R = pk2(r, r);
            mul2(A0, R); mul2(A1, R); mul2(A2, R); mul2(A3, R);
            mul2(B0, R); mul2(B1, R); mul2(B2, R); mul2(B3, R);
        }
        float pa[4] = {ex2(fa01.x - m), ex2(fa01.y - m), ex2(fa23.x - m), ex2(fa23.y - m)};
        float pb[4] = {ex2(fb01.x - m), ex2(fb01.y - m), ex2(fb23.x - m), ex2(fb23.y - m)};
        dA += (pa[0] + pa[1]) + (pa[2] + pa[3]);
        dB += (pb[0] + pb[1]) + (pb[2] + pb[3]);
        vacc(k4a, pa, A0, A1, A2, A3);
        vacc(k4b, pb, B0, B1, B2, B3);
    }
    // merge odd-quad set into even-quad set
    add2(A0, B0); add2(A1, B1); add2(A2, B2); add2(A3, B3);
    float denom = dA + dB;

    // possible leftover full quad
    if (i < nquad) {
        const int k4 = i << 2;
        float2 f01, f23;
        scoreq(k4, f01, f23);
        float qm = fmaxf(fmaxf(f01.x, f01.y), fmaxf(f23.x, f23.y));
        if (qm > m) {
            float r = ex2(m - qm);
            m = qm; denom *= r;
            unsigned long long R = pk2(r, r);
            mul2(A0, R); mul2(A1, R); mul2(A2, R); mul2(A3, R);
        }
        float p[4] = {ex2(f01.x - m), ex2(f01.y - m), ex2(f23.x - m), ex2(f23.y - m)};
        denom += (p[0] + p[1]) + (p[2] + p[3]);
        vacc(k4, p, A0, A1, A2, A3);
    }
    // scalar tail keys (nquad*4 .. q)
    for (int k = nquad << 2; k < n; k++) {
        float s = fmaf(qs0, sKt[0][k], fmaf(qs1, sKt[1][k], fmaf(qs2, sKt[2][k], qs3 * sKt[3][k])));
        if (s > m) {
            float r = ex2(m - s);
            m = s; denom *= r;
            unsigned long long R = pk2(r, r);
            mul2(A0, R); mul2(A1, R); mul2(A2, R); mul2(A3, R);
        }
        float p = ex2(s - m);
        denom += p;
        unsigned long long P = pk2(p, p);
        const float* vb = &sV[k * 8];
        ulonglong2 va = *(const ulonglong2*)(vb);
        ulonglong2 vc = *(const ulonglong2*)(vb + 4);
        fma2(A0, P, va.x); fma2(A1, P, va.y); fma2(A2, P, vc.x); fma2(A3, P, vc.y);
    }

    // masked-zero tail: weight ex2(-m) per masked key, V via strict suffix sums
    {
        float pm = ex2(-m);
        denom += (float)(SEQ - 1 - q) * pm;
        unsigned long long P = pk2(pm, pm);
        fma2(A0, P, pk2(suf[0], suf[1]));
        fma2(A1, P, pk2(suf[2], suf[3]));
        fma2(A2, P, pk2(suf[4], suf[5]));
        fma2(A3, P, pk2(suf[6], suf[7]));
    }

    const float inv = 1.0f / denom;
    float2 o0 = up2(A0), o1 = up2(A1), o2 = up2(A2), o3 = up2(A3);
    float vals[8] = {o0.x * inv, o0.y * inv, o1.x * inv, o1.y * inv,
                     o2.x * inv, o2.y * inv, o3.x * inv, o3.y * inv};

    __align__(16) __nv_bfloat16 H[8], M[8], L[8];
#pragma unroll
    for (int d = 0; d < 8; d++) split3(vals[d], H[d], M[d], L[d]);
    __nv_bfloat16* ob = OutS + (size_t)rowbase * KEXT + h * 8;
    *(uint4*)(ob)        = *(uint4*)H;
    *(uint4*)(ob + 512)  = *(uint4*)H;
    *(uint4*)(ob + 1024) = *(uint4*)M;
    *(uint4*)(ob + 1536) = *(uint4*)H;
    *(uint4*)(ob + 2048) = *(uint4*)L;
    *(uint4*)(ob + 2560) = *(uint4*)M;
}

// ---------------- NON-CAUSAL attention: 2 queries/thread, online softmax ----------------
__global__ __launch_bounds__(256, 2) void attnX_k(
    const float* __restrict__ Qa, const float* __restrict__ Qb,
    const float* __restrict__ KVbuf, float* __restrict__ Out)
{
    __shared__ float sKt[4][512];                 // K transposed: [dim][key]
    __shared__ __align__(16) float sV[512 * 8];   // V row-major:  [key][dim]

    const int bh = blockIdx.x;
    const int h = bh & 63, b = bh >> 6;
    const int t = threadIdx.x;

#pragma unroll
    for (int rr = 0; rr < 2; rr++) {
        const int row = t + rr * 256;
        const float* kv = KVbuf + (size_t)(b * SEQ + row) * 768;
        float4 kk = *(const float4*)(kv + h * 4);
        sKt[0][row] = kk.x; sKt[1][row] = kk.y; sKt[2][row] = kk.z; sKt[3][row] = kk.w;
        float4 v0 = *(const float4*)(kv + 256 + h * 8);
        float4 v1 = *(const float4*)(kv + 256 + h * 8 + 4);
        *(float4*)&sV[row * 8] = v0;
        *(float4*)&sV[row * 8 + 4] = v1;
    }
    __syncthreads();

    const float SCQ = 0.72134752044448170f;  // 0.5 * log2(e)
    unsigned long long aq1[4], aq2[4];
#pragma unroll
    for (int rr = 0; rr < 2; rr++) {
        const size_t row = (size_t)(b * SEQ + t + rr * 256);
        float4 qv = *(const float4*)(Qa + row * 256 + h * 4);
        float4 q2v = *(const float4*)(Qb + row * 256 + h * 4);
        qv.x += q2v.x; qv.y += q2v.y; qv.z += q2v.z; qv.w += q2v.w;
        unsigned long long* aq = rr ? aq2 : aq1;
        aq[0] = pk2(qv.x * SCQ, qv.x * SCQ);
        aq[1] = pk2(qv.y * SCQ, qv.y * SCQ);
        aq[2] = pk2(qv.z * SCQ, qv.z * SCQ);
        aq[3] = pk2(qv.w * SCQ, qv.w * SCQ);
    }

    float m1 = -1e30f, m2 = -1e30f;
    float d1 = 0.f, d2 = 0.f;
    unsigned long long A1[4] = {0ULL, 0ULL, 0ULL, 0ULL};
    unsigned long long A2[4] = {0ULL, 0ULL, 0ULL, 0ULL};

    auto step = [&](const float* s, float& m, float& dn, unsigned long long* A,
                    const ulonglong2* vv) {
        float qm = fmaxf(fmaxf(s[0], s[1]), fmaxf(s[2], s[3]));
        if (qm > m) {
            float r = ex2(m - qm);
            m = qm; dn *= r;
            unsigned long long R = pk2(r, r);
            mul2(A[0], R); mul2(A[1], R); mul2(A[2], R); mul2(A[3], R);
        }
        float p0 = ex2(s[0] - m), p1 = ex2(s[1] - m);
        float p2 = ex2(s[2] - m), p3 = ex2(s[3] - m);
        dn += (p0 + p1) + (p2 + p3);
        unsigned long long P;
        P = pk2(p0, p0);
        fma2(A[0], P, vv[0].x); fma2(A[1], P, vv[0].y); fma2(A[2], P, vv[1].x); fma2(A[3], P, vv[1].y);
        P = pk2(p1, p1);
        fma2(A[0], P, vv[2].x); fma2(A[1], P, vv[2].y); fma2(A[2], P, vv[3].x); fma2(A[3], P, vv[3].y);
        P = pk2(p2, p2);
        fma2(A[0], P, vv[4].x); fma2(A[1], P, vv[4].y); fma2(A[2], P, vv[5].x); fma2(A[3], P, vv[5].y);
        P = pk2(p3, p3);
        fma2(A[0], P, vv[6].x); fma2(A[1], P, vv[6].y); fma2(A[2], P, vv[7].x); fma2(A[3], P, vv[7].y);
    };

    for (int i = 0; i < 128; i++) {
        const int k4 = i << 2;
        ulonglong2 kq[4], vv[8];
        kq[0] = *(const ulonglong2*)&sKt[0][k4];
        kq[1] = *(const ulonglong2*)&sKt[1][k4];
        kq[2] = *(const ulonglong2*)&sKt[2][k4];
        kq[3] = *(const ulonglong2*)&sKt[3][k4];
        const float* vb = &sV[k4 * 8];
#pragma unroll
        for (int j = 0; j < 4; j++) {
            vv[2 * j]     = *(const ulonglong2*)(vb + j * 8);
            vv[2 * j + 1] = *(const ulonglong2*)(vb + j * 8 + 4);
        }
        float s1[4], s2[4];
        {
            unsigned long long s01 = 0ULL, s23 = 0ULL;
            fma2(s01, aq1[0], kq[0].x); fma2(s23, aq1[0], kq[0].y);
            fma2(s01, aq1[1], kq[1].x); fma2(s23, aq1[1], kq[1].y);
            fma2(s01, aq1[2], kq[2].x); fma2(s23, aq1[2], kq[2].y);
            fma2(s01, aq1[3], kq[3].x); fma2(s23, aq1[3], kq[3].y);
            float2 f01 = up2(s01), f23 = up2(s23);
            s1[0] = f01.x; s1[1] = f01.y; s1[2] = f23.x; s1[3] = f23.y;
        }
        {
            unsigned long long s01 = 0ULL, s23 = 0ULL;
            fma2(s01, aq2[0], kq[0].x); fma2(s23, aq2[0], kq[0].y);
            fma2(s01, aq2[1], kq[1].x); fma2(s23, aq2[1], kq[1].y);
            fma2(s01, aq2[2], kq[2].x); fma2(s23, aq2[2], kq[2].y);
            fma2(s01, aq2[3], kq[3].x); fma2(s23, aq2[3], kq[3].y);
            float2 f01 = up2(s01), f23 = up2(s23);
            s2[0] = f01.x; s2[1] = f01.y; s2[2] = f23.x; s2[3] = f23.y;
        }
        step(s1, m1, d1, A1, vv);
        step(s2, m2, d2, A2, vv);
    }

#pragma unroll
    for (int rr = 0; rr < 2; rr++) {
        const unsigned long long* A = rr ? A2 : A1;
        const float inv = 1.0f / (rr ? d2 : d1);
        float2 o0 = up2(A[0]), o1 = up2(A[1]), o2 = up2(A[2]), o3 = up2(A[3]);
        float* o = Out + (size_t)(b * SEQ + t + rr * 256) * DM + h * 8;
        *(float4*)(o)     = make_float4(o0.x * inv, o0.y * inv, o1.x * inv, o1.y * inv);
        *(float4*)(o + 4) = make_float4(o2.x * inv, o2.y * inv, o3.x * inv, o3.y * inv);
    }
}

// ---------------- Residual + LayerNorm + FFN (hidden=10) fused ----------------
#define HIDD 10
__global__ __launch_bounds__(256) void lnffn_k(
    const float* __restrict__ x, const float* __restrict__ fx,
    const float* __restrict__ lg, const float* __restrict__ lb,
    const float* __restrict__ w1, const float* __restrict__ b1,
    const float* __restrict__ w2, const float* __restrict__ b2,
    float* __restrict__ out)
{
    const int row = blockIdx.x;
    const int t = threadIdx.x;
    const int warp = t >> 5, lane = t & 31;

    const float* xr = x + row * DM;
    const float* fr = fx + row * DM;
    float v0 = xr[t] + fr[t];
    float v1 = xr[t + 256] + fr[t + 256];

    float s = v0 + v1;
    float ss = v0 * v0 + v1 * v1;
#pragma unroll
    for (int o = 16; o > 0; o >>= 1) {
        s  += __shfl_down_sync(0xffffffffu, s,  o);
        ss += __shfl_down_sync(0xffffffffu, ss, o);
    }
    __shared__ float rs[8], rss[8];
    if (lane == 0) { rs[warp] = s; rss[warp] = ss; }
    __syncthreads();
    float S = 0.f, SS = 0.f;
#pragma unroll
    for (int w = 0; w < 8; w++) { S += rs[w]; SS += rss[w]; }
    const float mu = S * (1.0f / DM);
    const float var = SS * (1.0f / DM) - mu * mu;
    const float rstd = rsqrtf(var + 1e-5f);

    const float y0 = (v0 - mu) * rstd * lg[t] + lb[t];
    const float y1 = (v1 - mu) * rstd * lg[t + 256] + lb[t + 256];

    float pj[HIDD];
#pragma unroll
    for (int j = 0; j < HIDD; j++)
        pj[j] = y0 * __ldg(&w1[j * DM + t]) + y1 * __ldg(&w1[j * DM + t + 256]);
#pragma unroll
    for (int j = 0; j < HIDD; j++)
#pragma unroll
        for (int o = 16; o > 0; o >>= 1)
            pj[j] += __shfl_down_sync(0xffffffffu, pj[j], o);

    __shared__ float hred[8][HIDD];
    if (lane == 0)
#pragma unroll
        for (int j = 0; j < HIDD; j++) hred[warp][j] = pj[j];
    __syncthreads();

    __shared__ float sh[HIDD];
    if (t < HIDD) {
        float hv = b1[t];
#pragma unroll
        for (int w = 0; w < 8; w++) hv += hred[w][t];
        sh[t] = fmaxf(hv, 0.f);
    }
    __syncthreads();

    float o0 = b2[t], o1 = b2[t + 256];
#pragma unroll
    for (int j = 0; j < HIDD; j++) {
        const float hj = sh[j];
        o0 = fmaf(hj, __ldg(&w2[t * HIDD + j]), o0);
        o1 = fmaf(hj, __ldg(&w2[(t + 256) * HIDD + j]), o1);
    }
    out[row * DM + t] = o0;
    out[row * DM + t + 256] = o1;
}

// ---------------- launch ----------------
extern "C" void kernel_launch(void* const* d_in, const int* in_sizes, int n_in,
                              void* d_out, int out_size)
{
    const float* x   = (const float*)d_in[0];
    const float* xe  = (const float*)d_in[1];
    const float* Wq  = (const float*)d_in[2];
    const float* Wk  = (const float*)d_in[3];
    const float* Wv  = (const float*)d_in[4];
    const float* lg  = (const float*)d_in[5];
    const float* lb  = (const float*)d_in[6];
    const float* w1  = (const float*)d_in[7];
    const float* b1  = (const float*)d_in[8];
    const float* w2  = (const float*)d_in[9];
    const float* b2  = (const float*)d_in[10];
    float* out = (float*)d_out;

    float *qkv, *kvenc, *q2a, *q2b, *fx2;
    __nv_bfloat16 *xs, *xes, *fxs, *ball;
    cudaGetSymbolAddress((void**)&qkv,   g_qkv);
    cudaGetSymbolAddress((void**)&kvenc, g_kvenc);
    cudaGetSymbolAddress((void**)&q2a,   g_q2a);
    cudaGetSymbolAddress((void**)&q2b,   g_q2b);
    cudaGetSymbolAddress((void**)&fx2,   g_fx2);
    cudaGetSymbolAddress((void**)&xs,    g_xs);
    cudaGetSymbolAddress((void**)&xes,   g_xes);
    cudaGetSymbolAddress((void**)&fxs,   g_fxs);
    cudaGetSymbolAddress((void**)&ball,  g_ball);

    cudaFuncSetAttribute(proj_k,   cudaFuncAttributeMaxDynamicSharedMemorySize, SMEM_MM);
    cudaFuncSetAttribute(crossq_k, cudaFuncAttributeMaxDynamicSharedMemorySize, SMEM_MM);

    // split inputs + weights into 6-segment bf16 K-extension
    splitAB_k<<<16384, 256>>>(x, xe, xs, xes);
    splitW_k<<<dim3(16, 56), dim3(32, 8)>>>(Wq, Wk, Wv, ball);

    // fused projections (KC64 + ldmatrix; best-measured GEMM)
    proj_k<<<448, 256, SMEM_MM>>>(xs, xes, ball, qkv, kvenc);

    // self-attention (1q/thread, single-pass online, dual acc sets)
    attnC_k<<<512, 512>>>(qkv, fxs);

    // cross-attention Q projection (split-K=2 over segment halves)
    crossq_k<<<128, 256, SMEM_MM>>>(fxs, ball, q2a, q2b);

    // cross-attention (2q/thread online; best-measured), Q = q2a + q2b
    attnX_k<<<512, 256>>>(q2a, q2b, kvenc, fx2);

    // residual + LN + FFN
    lnffn_k<<<4096, 256>>>(x, fx2, lg, lb, w1, b1, w2, b2, out);
}

// round 16
// speedup vs baseline: 1.1940x; 1.0068x over previous
#include <cuda_runtime.h>
#include <cuda_bf16.h>
#include <cstdint>

#define BS 8
#define SEQ 512
#define DM 512
#define NROW (BS*SEQ)          // 4096
#define KEXT 3072              // 6 segments x 512
#define KC 64                  // GEMM k-chunk

// ---------------- scratch (no allocation allowed) ----------------
__device__ __align__(16) float g_qkv[NROW * 1024];    // [Q(256)|K(256)|V(512)] self
__device__ __align__(16) float g_kvenc[NROW * 768];   // [K(256)|V(512)] encoder
__device__ __align__(16) float g_q2a[NROW * 256];     // cross-Q split-K partial 0
__device__ __align__(16) float g_q2b[NROW * 256];     // cross-Q split-K partial 1
__device__ __align__(16) float g_fx2[NROW * 512];     // cross-attn output
__device__ __align__(16) __nv_bfloat16 g_xs [NROW * KEXT];   // x   split-extended
__device__ __align__(16) __nv_bfloat16 g_xes[NROW * KEXT];   // xe  split-extended
__device__ __align__(16) __nv_bfloat16 g_fxs[NROW * KEXT];   // fx  split-extended
__device__ __align__(16) __nv_bfloat16 g_ball[1792 * KEXT];  // [Wq|Wk|Wv|Wk|Wv]^T split

// ---------------- helpers ----------------
__device__ __forceinline__ uint32_t smem_u32(const void* p) {
    uint32_t a;
    asm("{ .reg .u64 t; cvta.to.shared.u64 t, %1; cvt.u32.u64 %0, t; }" : "=r"(a) : "l"(p));
    return a;
}
__device__ __forceinline__ float ex2(float x) {
    float y; asm("ex2.approx.f32 %0, %1;" : "=f"(y) : "f"(x)); return y;
}
__device__ __forceinline__ unsigned long long pk2(float x, float y) {
    unsigned long long r; asm("mov.b64 %0, {%1,%2};" : "=l"(r) : "f"(x), "f"(y)); return r;
}
__device__ __forceinline__ void fma2(unsigned long long& d, unsigned long long a, unsigned long long b) {
    asm("fma.rn.f32x2 %0, %1, %2, %0;" : "+l"(d) : "l"(a), "l"(b));
}
__device__ __forceinline__ void mul2(unsigned long long& d, unsigned long long a) {
    asm("mul.rn.f32x2 %0, %0, %1;" : "+l"(d) : "l"(a));
}
__device__ __forceinline__ void add2(unsigned long long& d, unsigned long long a) {
    asm("add.rn.f32x2 %0, %0, %1;" : "+l"(d) : "l"(a));
}
__device__ __forceinline__ float2 up2(unsigned long long v) {
    float2 r; asm("mov.b64 {%0,%1}, %2;" : "=f"(r.x), "=f"(r.y) : "l"(v)); return r;
}
__device__ __forceinline__ void cpasync16(uint32_t dst, const void* src) {
    asm volatile("cp.async.cg.shared.global [%0], [%1], 16;" :: "r"(dst), "l"(src));
}
__device__ __forceinline__ void ldsm4(uint32_t& r0, uint32_t& r1, uint32_t& r2, uint32_t& r3, uint32_t addr) {
    asm volatile("ldmatrix.sync.aligned.m8n8.x4.shared.b16 {%0,%1,%2,%3}, [%4];"
                 : "=r"(r0), "=r"(r1), "=r"(r2), "=r"(r3) : "r"(addr));
}

__device__ __forceinline__ void split3(float v, __nv_bfloat16& h, __nv_bfloat16& m, __nv_bfloat16& l) {
    h = __float2bfloat16(v);
    float r1 = v - __bfloat162float(h);
    m = __float2bfloat16(r1);
    float r2 = r1 - __bfloat162float(m);
    l = __float2bfloat16(r2);
}

// ---------------- split kernels ----------------
// A segments: [hi, hi, mid, hi, lo, mid]; handles x and xe in one launch.
__global__ __launch_bounds__(256) void splitAB_k(const float* __restrict__ x, const float* __restrict__ xe,
                                                 __nv_bfloat16* __restrict__ xs, __nv_bfloat16* __restrict__ xes)
{
    int gid = blockIdx.x * 256 + threadIdx.x;   // 2 * NROW*512
    const float* in; __nv_bfloat16* out; int id;
    if (gid < NROW * 512) { in = x; out = xs; id = gid; }
    else { in = xe; out = xes; id = gid - NROW * 512; }
    int r = id >> 9, c = id & 511;
    __nv_bfloat16 h, m, l;
    split3(in[id], h, m, l);
    __nv_bfloat16* o = out + (size_t)r * KEXT + c;
    o[0] = h; o[512] = h; o[1024] = m; o[1536] = h; o[2048] = l; o[2560] = m;
}

// B rows: g_ball[n][k] = W[k][n], segments [hi, mid, hi, lo, hi, mid]
__global__ void splitW_k(const float* __restrict__ Wq, const float* __restrict__ Wk,
                         const float* __restrict__ Wv, __nv_bfloat16* __restrict__ out)
{
    __shared__ float s[32][33];
    const int k0 = blockIdx.x * 32, n0 = blockIdx.y * 32;
    const int tx = threadIdx.x, ty = threadIdx.y;   // 32 x 8

    const float* src; int col0, ldw;
    if      (n0 < 256)  { src = Wq; col0 = n0;        ldw = 256; }
    else if (n0 < 512)  { src = Wk; col0 = n0 - 256;  ldw = 256; }
    else if (n0 < 1024) { src = Wv; col0 = n0 - 512;  ldw = 512; }
    else if (n0 < 1280) { src = Wk; col0 = n0 - 1024; ldw = 256; }
    else                { src = Wv; col0 = n0 - 1280; ldw = 512; }

#pragma unroll
    for (int i = 0; i < 4; i++) {
        int kk = ty + i * 8;
        s[kk][tx] = src[(k0 + kk) * ldw + col0 + tx];
    }
    __syncthreads();
#pragma unroll
    for (int i = 0; i < 4; i++) {
        int nn = ty + i * 8;
        __nv_bfloat16 h, m, l;
        split3(s[tx][nn], h, m, l);
        __nv_bfloat16* o = out + (size_t)(n0 + nn) * KEXT + k0 + tx;
        o[0] = h; o[512] = m; o[1024] = h; o[1536] = l; o[2048] = h; o[2560] = m;
    }
}

// ---------------- mma.sync GEMM body: 128x128 CTA tile, KC=64, ldmatrix ----------------
#define ROWB 144                     // 72 bf16 per row (64 + 8 pad), bytes
#define STAGE_B (128 * ROWB)         // bytes per stage per matrix
#define SMEM_MM (4 * STAGE_B)        // total dynamic smem (73728)

__device__ __forceinline__ void mma_body(char* smem,
    const __nv_bfloat16* __restrict__ A, const __nv_bfloat16* __restrict__ B,
    float* __restrict__ C, int ldc, int nch)
{
    const int tid = threadIdx.x;
    const int wid = tid >> 5, lane = tid & 31;

    const uint32_t sAb = smem_u32(smem);
    const uint32_t sBb = sAb + 2 * STAGE_B;

    auto issue = [&](int c, int buf) {
#pragma unroll
        for (int i = 0; i < 4; i++) {
            int g = tid + i * 256;           // 1024 granules of 16B
            int r = g >> 3, j = g & 7;
            uint32_t so = (uint32_t)buf * STAGE_B + r * ROWB + j * 16;
            cpasync16(sAb + so, (const char*)(A + (size_t)r * KEXT + c * KC + j * 8));
            cpasync16(sBb + so, (const char*)(B + (size_t)r * KEXT + c * KC + j * 8));
        }
    };

    issue(0, 0);
    asm volatile("cp.async.commit_group;" ::: "memory");
    issue(1, 1);
    asm volatile("cp.async.commit_group;" ::: "memory");

    float acc[4][4][4];
#pragma unroll
    for (int i = 0; i < 4; i++)
#pragma unroll
        for (int j = 0; j < 4; j++)
#pragma unroll
            for (int k = 0; k < 4; k++) acc[i][j][k] = 0.f;

    const int wm = wid >> 2, wn = wid & 3;
    const uint32_t lrow = lane & 15, lhalf = lane >> 4;
    const uint32_t aoff = (wm * 64 + lrow) * ROWB + lhalf * 16;
    const uint32_t boff = (wn * 32 + lrow) * ROWB + lhalf * 16;

    for (int c = 0; c < nch; c++) {
        asm volatile("cp.async.wait_group 1;" ::: "memory");
        __syncthreads();
        const uint32_t sa = sAb + (uint32_t)(c & 1) * STAGE_B + aoff;
        const uint32_t sb = sBb + (uint32_t)(c & 1) * STAGE_B + boff;

#pragma unroll
        for (int ks = 0; ks < 4; ks++) {
            uint32_t af[4][4], bf[4][2];
#pragma unroll
            for (int am = 0; am < 4; am++)
                ldsm4(af[am][0], af[am][1], af[am][2], af[am][3],
                      sa + am * 16 * ROWB + ks * 32);
#pragma unroll
            for (int anp = 0; anp < 2; anp++) {
                uint32_t r0, r1, r2, r3;
                ldsm4(r0, r1, r2, r3, sb + anp * 16 * ROWB + ks * 32);
                bf[2 * anp][0] = r0; bf[2 * anp + 1][0] = r1;
                bf[2 * anp][1] = r2; bf[2 * anp + 1][1] = r3;
            }
#pragma unroll
            for (int am = 0; am < 4; am++)
#pragma unroll
                for (int an = 0; an < 4; an++) {
                    asm volatile(
                        "mma.sync.aligned.m16n8k16.row.col.f32.bf16.bf16.f32 "
                        "{%0,%1,%2,%3}, {%4,%5,%6,%7}, {%8,%9}, {%0,%1,%2,%3};"
                        : "+f"(acc[am][an][0]), "+f"(acc[am][an][1]),
                          "+f"(acc[am][an][2]), "+f"(acc[am][an][3])
                        : "r"(af[am][0]), "r"(af[am][1]), "r"(af[am][2]), "r"(af[am][3]),
                          "r"(bf[an][0]), "r"(bf[an][1]));
                }
        }
        __syncthreads();
        if (c + 2 < nch) issue(c + 2, c & 1);
        asm volatile("cp.async.commit_group;" ::: "memory");
    }

#pragma unroll
    for (int am = 0; am < 4; am++) {
#pragma unroll
        for (int an = 0; an < 4; an++) {
            int r0 = wm * 64 + am * 16 + (lane >> 2);
            int cc = wn * 32 + an * 8 + (lane & 3) * 2;
            *(float2*)&C[r0 * ldc + cc]       = make_float2(acc[am][an][0], acc[am][an][1]);
            *(float2*)&C[(r0 + 8) * ldc + cc] = make_float2(acc[am][an][2], acc[am][an][3]);
        }
    }
}

// fused projections, 448 blocks, heavy (6-limb) first, light (3-limb enc-V) last
__global__ __launch_bounds__(256, 2) void proj_k(
    const __nv_bfloat16* __restrict__ xs, const __nv_bfloat16* __restrict__ xes,
    const __nv_bfloat16* __restrict__ ball, float* __restrict__ qkv, float* __restrict__ kvenc)
{
    extern __shared__ char smem[];
    const int bid = blockIdx.x;
    const __nv_bfloat16 *A, *B; float* C; int ldc, nch, bx, by;
    if (bid < 256) {
        bx = bid & 7; by = bid >> 3;
        A = xs; B = ball; C = qkv; ldc = 1024; nch = 48;
    } else if (bid < 320) {
        int i = bid - 256; bx = i & 1; by = i >> 1;
        A = xes; B = ball + (size_t)1024 * KEXT; C = kvenc; ldc = 768; nch = 48;
    } else {
        int i = bid - 320; bx = 2 + (i & 3); by = i >> 2;
        A = xes; B = ball + (size_t)1024 * KEXT; C = kvenc; ldc = 768; nch = 24;
    }
    mma_body(smem, A + (size_t)by * 128 * KEXT, B + (size_t)bx * 128 * KEXT,
             C + (size_t)by * 128 * ldc + bx * 128, ldc, nch);
}

// cross-Q GEMM: split-K=2 over the 6 segments: half0 = [h,h,m], half1 = [h,l,m]
__global__ __launch_bounds__(256, 2) void crossq_k(
    const __nv_bfloat16* __restrict__ fxs, const __nv_bfloat16* __restrict__ ball,
    float* __restrict__ q2a, float* __restrict__ q2b)
{
    extern __shared__ char smem[];
    const int bid = blockIdx.x;            // 128
    const int half = bid >> 6;
    const int i = bid & 63;
    const int bx = i & 1, by = i >> 1;
    const __nv_bfloat16* A = fxs + half * 1536;
    const __nv_bfloat16* B = ball + half * 1536;
    float* C = half ? q2b : q2a;
    mma_body(smem, A + (size_t)by * 128 * KEXT, B + (size_t)bx * 128 * KEXT,
             C + (size_t)by * 128 * 256 + bx * 128, 256, 24);
}

// ---------------- CAUSAL attention: single-pass online, SMSP-balanced ----------------
// Warp w (SMSP s=w&3, j=w>>2) handles query block perm(j,s) in {s, 7-s, 8+s, 15-s}
// so every SMSP carries equal total trip count. Strict V suffix sums pass through
// smem sSuf (padded rows). Masked-zero quirk preserved exactly.
__global__ __launch_bounds__(512, 2) void attnC_k(
    const float* __restrict__ QKV, __nv_bfloat16* __restrict__ OutS)
{
    __shared__ float sKt[4][512];                 // K transposed: [dim][key]
    __shared__ __align__(16) float sV[512 * 8];   // V row-major:  [key][dim]
    __shared__ float sWS[16][8];                  // warp totals for suffix scan
    __shared__ float sSuf[513][9];                // inclusive V suffix sums (padded)

    const int bh = blockIdx.x;
    const int h = bh & 63, b = bh >> 6;
    const int t = threadIdx.x, lane = t & 31, wid = t >> 5;

    // load K,V row t
    {
        const float* kv = QKV + (size_t)(b * SEQ + t) * 1024;
        float4 kk = *(const float4*)(kv + 256 + h * 4);
        sKt[0][t] = kk.x; sKt[1][t] = kk.y; sKt[2][t] = kk.z; sKt[3][t] = kk.w;
        float4 v0 = *(const float4*)(kv + 512 + h * 8);
        float4 v1 = *(const float4*)(kv + 512 + h * 8 + 4);
        *(float4*)&sV[t * 8] = v0;
        *(float4*)&sV[t * 8 + 4] = v1;

        // inclusive suffix scan for row t -> sSuf[t]
        float suf[8] = {v0.x, v0.y, v0.z, v0.w, v1.x, v1.y, v1.z, v1.w};
#pragma unroll
        for (int off = 1; off < 32; off <<= 1) {
#pragma unroll
            for (int d = 0; d < 8; d++) {
                float o = __shfl_down_sync(0xffffffffu, suf[d], off);
                if (lane + off < 32) suf[d] += o;
            }
        }
        if (lane == 0) {
#pragma unroll
            for (int d = 0; d < 8; d++) sWS[wid][d] = suf[d];
        }
        __syncthreads();
        for (int w = wid + 1; w < 16; w++)
#pragma unroll
            for (int d = 0; d < 8; d++) suf[d] += sWS[w][d];
#pragma unroll
        for (int d = 0; d < 8; d++) sSuf[t][d] = suf[d];
        if (t == 0) {
#pragma unroll
            for (int d = 0; d < 8; d++) sSuf[512][d] = 0.f;
        }
    }
    __syncthreads();

    // SMSP-balanced query block assignment
    const int s = wid & 3, j = wid >> 2;
    const int qb = (j == 0) ? s : (j == 1) ? (7 - s) : (j == 2) ? (8 + s) : (15 - s);
    const int q = qb * 32 + lane;
    const size_t rowbase = (size_t)(b * SEQ + q);

    const float SCQ = 0.72134752044448170f;  // 0.5 * log2(e)
    float4 qv = *(const float4*)(QKV + rowbase * 1024 + h * 4);
    const float qs0 = qv.x * SCQ, qs1 = qv.y * SCQ, qs2 = qv.z * SCQ, qs3 = qv.w * SCQ;
    unsigned long long aq0 = pk2(qs0, qs0), aq1 = pk2(qs1, qs1);
    unsigned long long aq2 = pk2(qs2, qs2), aq3 = pk2(qs3, qs3);

    const int n = q + 1;
    const int nquad = n >> 2;

    float m = 0.f;        // masked zeros participate in softmax
    float dA = 0.f, dB = 0.f;
    unsigned long long A0 = 0, A1 = 0, A2 = 0, A3 = 0;
    unsigned long long B0 = 0, B1 = 0, B2 = 0, B3 = 0;

    auto scoreq = [&](int k4, float2& f01, float2& f23) {
        ulonglong2 k0 = *(const ulonglong2*)&sKt[0][k4];
        ulonglong2 k1 = *(const ulonglong2*)&sKt[1][k4];
        ulonglong2 k2 = *(const ulonglong2*)&sKt[2][k4];
        ulonglong2 k3 = *(const ulonglong2*)&sKt[3][k4];
        unsigned long long s01 = 0ULL, s23 = 0ULL;
        fma2(s01, aq0, k0.x); fma2(s23, aq0, k0.y);
        fma2(s01, aq1, k1.x); fma2(s23, aq1, k1.y);
        fma2(s01, aq2, k2.x); fma2(s23, aq2, k2.y);
        fma2(s01, aq3, k3.x); fma2(s23, aq3, k3.y);
        f01 = up2(s01); f23 = up2(s23);
    };
    auto vacc = [&](int k4, const float* p,
                    unsigned long long& X0, unsigned long long& X1,
                    unsigned long long& X2, unsigned long long& X3) {
        const float* vb = &sV[k4 * 8];
#pragma unroll
        for (int jj = 0; jj < 4; jj++) {
            unsigned long long P = pk2(p[jj], p[jj]);
            ulonglong2 va = *(const ulonglong2*)(vb + jj * 8);
            ulonglong2 vc = *(const ulonglong2*)(vb + jj * 8 + 4);
            fma2(X0, P, va.x); fma2(X1, P, va.y); fma2(X2, P, vc.x); fma2(X3, P, vc.y);
        }
    };

    int i = 0;
    for (; i + 2 <= nquad; i += 2) {
        const int k4a = i << 2, k4b = k4a + 4;
        float2 fa01, fa23, fb01, fb23;
        scoreq(k4a, fa01, fa23);
        scoreq(k4b, fb01, fb23);
        float qm = fmaxf(fmaxf(fmaxf(fa01.x, fa01.y), fmaxf(fa23.x, fa23.y)),
                         fmaxf(fmaxf(fb01.x, fb01.y), fmaxf(fb23.x, fb23.y)));
        if (qm > m) {
            float r = ex2(m - qm);
            m = qm; dA *= r; dB *= r;
            unsigned long long R = pk2(r, r);
            mul2(A0, R); mul2(A1, R); mul2(A2, R); mul2(A3, R);
            mul2(B0, R); mul2(B1, R); mul2(B2, R); mul2(B3, R);
        }
        float pa[4] = {ex2(fa01.x - m), ex2(fa01.y - m), ex2(fa23.x - m), ex2(fa23.y - m)};
        float pb[4] = {ex2(fb01.x - m), ex2(fb01.y - m), ex2(fb23.x - m), ex2(fb23.y - m)};
        dA += (pa[0] + pa[1]) + (pa[2] + pa[3]);
        dB += (pb[0] + pb[1]) + (pb[2] + pb[3]);
        vacc(k4a, pa, A0, A1, A2, A3);
        vacc(k4b, pb, B0, B1, B2, B3);
    }
    add2(A0, B0); add2(A1, B1); add2(A2, B2); add2(A3, B3);
    float denom = dA + dB;

    if (i < nquad) {
        const int k4 = i << 2;
        float2 f01, f23;
        scoreq(k4, f01, f23);
        float qm = fmaxf(fmaxf(f01.x, f01.y), fmaxf(f23.x, f23.y));
        if (qm > m) {
            float r = ex2(m - qm);
            m = qm; denom *= r;
            unsigned long long R = pk2(r, r);
            mul2(A0, R); mul2(A1, R); mul2(A2, R); mul2(A3, R);
        }
        float p[4] = {ex2(f01.x - m), ex2(f01.y - m), ex2(f23.x - m), ex2(f23.y - m)};
        denom += (p[0] + p[1]) + (p[2] + p[3]);
        vacc(k4, p, A0, A1, A2, A3);
    }
    for (int k = nquad << 2; k < n; k++) {
        float sc = fmaf(qs0, sKt[0][k], fmaf(qs1, sKt[1][k], fmaf(qs2, sKt[2][k], qs3 * sKt[3][k])));
        if (sc > m) {
            float r = ex2(m - sc);
            m = sc; denom *= r;
            unsigned long long R = pk2(r, r);
            mul2(A0, R); mul2(A1, R); mul2(A2, R); mul2(A3, R);
        }
        float p = ex2(sc - m);
        denom += p;
        unsigned long long P = pk2(p, p);
        const float* vb = &sV[k * 8];
        ulonglong2 va = *(const ulonglong2*)(vb);
        ulonglong2 vc = *(const ulonglong2*)(vb + 4);
        fma2(A0, P, va.x); fma2(A1, P, va.y); fma2(A2, P, vc.x); fma2(A3, P, vc.y);
    }

    // masked-zero tail: strict suffix sum from sSuf[q+1]
    {
        const float* sf = sSuf[q + 1];
        float pm = ex2(-m);
        denom += (float)(SEQ - 1 - q) * pm;
        unsigned long long P = pk2(pm, pm);
        fma2(A0, P, pk2(sf[0], sf[1]));
        fma2(A1, P, pk2(sf[2], sf[3]));
        fma2(A2, P, pk2(sf[4], sf[5]));
        fma2(A3, P, pk2(sf[6], sf[7]));
    }

    const float inv = 1.0f / denom;
    float2 o0 = up2(A0), o1 = up2(A1), o2 = up2(A2), o3 = up2(A3);
    float vals[8] = {o0.x * inv, o0.y * inv, o1.x * inv, o1.y * inv,
                     o2.x * inv, o2.y * inv, o3.x * inv, o3.y * inv};

    __align__(16) __nv_bfloat16 H[8], M[8], L[8];
#pragma unroll
    for (int d = 0; d < 8; d++) split3(vals[d], H[d], M[d], L[d]);
    __nv_bfloat16* ob = OutS + rowbase * KEXT + h * 8;
    *(uint4*)(ob)        = *(uint4*)H;
    *(uint4*)(ob + 512)  = *(uint4*)H;
    *(uint4*)(ob + 1024) = *(uint4*)M;
    *(uint4*)(ob + 1536) = *(uint4*)H;
    *(uint4*)(ob + 2048) = *(uint4*)L;
    *(uint4*)(ob + 2560) = *(uint4*)M;
}

// ---------------- NON-CAUSAL attention: 2 queries/thread, online softmax ----------------
__global__ __launch_bounds__(256, 2) void attnX_k(
    const float* __restrict__ Qa, const float* __restrict__ Qb,
    const float* __restrict__ KVbuf, float* __restrict__ Out)
{
    __shared__ float sKt[4][512];                 // K transposed: [dim][key]
    __shared__ __align__(16) float sV[512 * 8];   // V row-major:  [key][dim]

    const int bh = blockIdx.x;
    const int h = bh & 63, b = bh >> 6;
    const int t = threadIdx.x;

#pragma unroll
    for (int rr = 0; rr < 2; rr++) {
        const int row = t + rr * 256;
        const float* kv = KVbuf + (size_t)(b * SEQ + row) * 768;
        float4 kk = *(const float4*)(kv + h * 4);
        sKt[0][row] = kk.x; sKt[1][row] = kk.y; sKt[2][row] = kk.z; sKt[3][row] = kk.w;
        float4 v0 = *(const float4*)(kv + 256 + h * 8);
        float4 v1 = *(const float4*)(kv + 256 + h * 8 + 4);
        *(float4*)&sV[row * 8] = v0;
        *(float4*)&sV[row * 8 + 4] = v1;
    }
    __syncthreads();

    const float SCQ = 0.72134752044448170f;  // 0.5 * log2(e)
    unsigned long long aq1[4], aq2[4];
#pragma unroll
    for (int rr = 0; rr < 2; rr++) {
        const size_t row = (size_t)(b * SEQ + t + rr * 256);
        float4 qv = *(const float4*)(Qa + row * 256 + h * 4);
        float4 q2v = *(const float4*)(Qb + row * 256 + h * 4);
        qv.x += q2v.x; qv.y += q2v.y; qv.z += q2v.z; qv.w += q2v.w;
        unsigned long long* aq = rr ? aq2 : aq1;
        aq[0] = pk2(qv.x * SCQ, qv.x * SCQ);
        aq[1] = pk2(qv.y * SCQ, qv.y * SCQ);
        aq[2] = pk2(qv.z * SCQ, qv.z * SCQ);
        aq[3] = pk2(qv.w * SCQ, qv.w * SCQ);
    }

    float m1 = -1e30f, m2 = -1e30f;
    float d1 = 0.f, d2 = 0.f;
    unsigned long long A1[4] = {0ULL, 0ULL, 0ULL, 0ULL};
    unsigned long long A2[4] = {0ULL, 0ULL, 0ULL, 0ULL};

    auto step = [&](const float* s, float& m, float& dn, unsigned long long* A,
                    const ulonglong2* vv) {
        float qm = fmaxf(fmaxf(s[0], s[1]), fmaxf(s[2], s[3]));
        if (qm > m) {
            float r = ex2(m - qm);
            m = qm; dn *= r;
            unsigned long long R = pk2(r, r);
            mul2(A[0], R); mul2(A[1], R); mul2(A[2], R); mul2(A[3], R);
        }
        float p0 = ex2(s[0] - m), p1 = ex2(s[1] - m);
        float p2 = ex2(s[2] - m), p3 = ex2(s[3] - m);
        dn += (p0 + p1) + (p2 + p3);
        unsigned long long P;
        P = pk2(p0, p0);
        fma2(A[0], P, vv[0].x); fma2(A[1], P, vv[0].y); fma2(A[2], P, vv[1].x); fma2(A[3], P, vv[1].y);
        P = pk2(p1, p1);
        fma2(A[0], P, vv[2].x); fma2(A[1], P, vv[2].y); fma2(A[2], P, vv[3].x); fma2(A[3], P, vv[3].y);
        P = pk2(p2, p2);
        fma2(A[0], P, vv[4].x); fma2(A[1], P, vv[4].y); fma2(A[2], P, vv[5].x); fma2(A[3], P, vv[5].y);
        P = pk2(p3, p3);
        fma2(A[0], P, vv[6].x); fma2(A[1], P, vv[6].y); fma2(A[2], P, vv[7].x); fma2(A[3], P, vv[7].y);
    };

    for (int i = 0; i < 128; i++) {
        const int k4 = i << 2;
        ulonglong2 kq[4], vv[8];
        kq[0] = *(const ulonglong2*)&sKt[0][k4];
        kq[1] = *(const ulonglong2*)&sKt[1][k4];
        kq[2] = *(const ulonglong2*)&sKt[2][k4];
        kq[3] = *(const ulonglong2*)&sKt[3][k4];
        const float* vb = &sV[k4 * 8];
#pragma unroll
        for (int j = 0; j < 4; j++) {
            vv[2 * j]     = *(const ulonglong2*)(vb + j * 8);
            vv[2 * j + 1] = *(const ulonglong2*)(vb + j * 8 + 4);
        }
        float s1[4], s2[4];
        {
            unsigned long long s01 = 0ULL, s23 = 0ULL;
            fma2(s01, aq1[0], kq[0].x); fma2(s23, aq1[0], kq[0].y);
            fma2(s01, aq1[1], kq[1].x); fma2(s23, aq1[1], kq[1].y);
            fma2(s01, aq1[2], kq[2].x); fma2(s23, aq1[2], kq[2].y);
            fma2(s01, aq1[3], kq[3].x); fma2(s23, aq1[3], kq[3].y);
            float2 f01 = up2(s01), f23 = up2(s23);
            s1[0] = f01.x; s1[1] = f01.y; s1[2] = f23.x; s1[3] = f23.y;
        }
        {
            unsigned long long s01 = 0ULL, s23 = 0ULL;
            fma2(s01, aq2[0], kq[0].x); fma2(s23, aq2[0], kq[0].y);
            fma2(s01, aq2[1], kq[1].x); fma2(s23, aq2[1], kq[1].y);
            fma2(s01, aq2[2], kq[2].x); fma2(s23, aq2[2], kq[2].y);
            fma2(s01, aq2[3], kq[3].x); fma2(s23, aq2[3], kq[3].y);
            float2 f01 = up2(s01), f23 = up2(s23);
            s2[0] = f01.x; s2[1] = f01.y; s2[2] = f23.x; s2[3] = f23.y;
        }
        step(s1, m1, d1, A1, vv);
        step(s2, m2, d2, A2, vv);
    }

#pragma unroll
    for (int rr = 0; rr < 2; rr++) {
        const unsigned long long* A = rr ? A2 : A1;
        const float inv = 1.0f / (rr ? d2 : d1);
        float2 o0 = up2(A[0]), o1 = up2(A[1]), o2 = up2(A[2]), o3 = up2(A[3]);
        float* o = Out + (size_t)(b * SEQ + t + rr * 256) * DM + h * 8;
        *(float4*)(o)     = make_float4(o0.x * inv, o0.y * inv, o1.x * inv, o1.y * inv);
        *(float4*)(o + 4) = make_float4(o2.x * inv, o2.y * inv, o3.x * inv, o3.y * inv);
    }
}

// ---------------- Residual + LayerNorm + FFN (hidden=10) fused ----------------
#define HIDD 10
__global__ __launch_bounds__(256) void lnffn_k(
    const float* __restrict__ x, const float* __restrict__ fx,
    const float* __restrict__ lg, const float* __restrict__ lb,
    const float* __restrict__ w1, const float* __restrict__ b1,
    const float* __restrict__ w2, const float* __restrict__ b2,
    float* __restrict__ out)
{
    const int row = blockIdx.x;
    const int t = threadIdx.x;
    const int warp = t >> 5, lane = t & 31;

    const float* xr = x + row * DM;
    const float* fr = fx + row * DM;
    float v0 = xr[t] + fr[t];
    float v1 = xr[t + 256] + fr[t + 256];

    float s = v0 + v1;
    float ss = v0 * v0 + v1 * v1;
#pragma unroll
    for (int o = 16; o > 0; o >>= 1) {
        s  += __shfl_down_sync(0xffffffffu, s,  o);
        ss += __shfl_down_sync(0xffffffffu, ss, o);
    }
    __shared__ float rs[8], rss[8];
    if (lane == 0) { rs[warp] = s; rss[warp] = ss; }
    __syncthreads();
    float S = 0.f, SS = 0.f;
#pragma unroll
    for (int w = 0; w < 8; w++) { S += rs[w]; SS += rss[w]; }
    const float mu = S * (1.0f / DM);
    const float var = SS * (1.0f / DM) - mu * mu;
    const float rstd = rsqrtf(var + 1e-5f);

    const float y0 = (v0 - mu) * rstd * lg[t] + lb[t];
    const float y1 = (v1 - mu) * rstd * lg[t + 256] + lb[t + 256];

    float pj[HIDD];
#pragma unroll
    for (int j = 0; j < HIDD; j++)
        pj[j] = y0 * __ldg(&w1[j * DM + t]) + y1 * __ldg(&w1[j * DM + t + 256]);
#pragma unroll
    for (int j = 0; j < HIDD; j++)
#pragma unroll
        for (int o = 16; o > 0; o >>= 1)
            pj[j] += __shfl_down_sync(0xffffffffu, pj[j], o);

    __shared__ float hred[8][HIDD];
    if (lane == 0)
#pragma unroll
        for (int j = 0; j < HIDD; j++) hred[warp][j] = pj[j];
    __syncthreads();

    __shared__ float sh[HIDD];
    if (t < HIDD) {
        float hv = b1[t];
#pragma unroll
        for (int w = 0; w < 8; w++) hv += hred[w][t];
        sh[t] = fmaxf(hv, 0.f);
    }
    __syncthreads();

    float o0 = b2[t], o1 = b2[t + 256];
#pragma unroll
    for (int j = 0; j < HIDD; j++) {
        const float hj = sh[j];
        o0 = fmaf(hj, __ldg(&w2[t * HIDD + j]), o0);
        o1 = fmaf(hj, __ldg(&w2[(t + 256) * HIDD + j]), o1);
    }
    out[row * DM + t] = o0;
    out[row * DM + t + 256] = o1;
}

// ---------------- launch ----------------
extern "C" void kernel_launch(void* const* d_in, const int* in_sizes, int n_in,
                              void* d_out, int out_size)
{
    const float* x   = (const float*)d_in[0];
    const float* xe  = (const float*)d_in[1];
    const float* Wq  = (const float*)d_in[2];
    const float* Wk  = (const float*)d_in[3];
    const float* Wv  = (const float*)d_in[4];
    const float* lg  = (const float*)d_in[5];
    const float* lb  = (const float*)d_in[6];
    const float* w1  = (const float*)d_in[7];
    const float* b1  = (const float*)d_in[8];
    const float* w2  = (const float*)d_in[9];
    const float* b2  = (const float*)d_in[10];
    float* out = (float*)d_out;

    float *qkv, *kvenc, *q2a, *q2b, *fx2;
    __nv_bfloat16 *xs, *xes, *fxs, *ball;
    cudaGetSymbolAddress((void**)&qkv,   g_qkv);
    cudaGetSymbolAddress((void**)&kvenc, g_kvenc);
    cudaGetSymbolAddress((void**)&q2a,   g_q2a);
    cudaGetSymbolAddress((void**)&q2b,   g_q2b);
    cudaGetSymbolAddress((void**)&fx2,   g_fx2);
    cudaGetSymbolAddress((void**)&xs,    g_xs);
    cudaGetSymbolAddress((void**)&xes,   g_xes);
    cudaGetSymbolAddress((void**)&fxs,   g_fxs);
    cudaGetSymbolAddress((void**)&ball,  g_ball);

    cudaFuncSetAttribute(proj_k,   cudaFuncAttributeMaxDynamicSharedMemorySize, SMEM_MM);
    cudaFuncSetAttribute(crossq_k, cudaFuncAttributeMaxDynamicSharedMemorySize, SMEM_MM);

    // split inputs + weights into 6-segment bf16 K-extension
    splitAB_k<<<16384, 256>>>(x, xe, xs, xes);
    splitW_k<<<dim3(16, 56), dim3(32, 8)>>>(Wq, Wk, Wv, ball);

    // fused projections (KC64 + ldmatrix; best-measured GEMM)
    proj_k<<<448, 256, SMEM_MM>>>(xs, xes, ball, qkv, kvenc);

    // self-attention (single-pass online, SMSP-balanced warp mapping)
    attnC_k<<<512, 512>>>(qkv, fxs);

    // cross-attention Q projection (split-K=2 over segment halves)
    crossq_k<<<128, 256, SMEM_MM>>>(fxs, ball, q2a, q2b);

    // cross-attention (2q/thread online; best-measured), Q = q2a + q2b
    attnX_k<<<512, 256>>>(q2a, q2b, kvenc, fx2);

    // residual + LN + FFN
    lnffn_k<<<4096, 256>>>(x, fx2, lg, lb, w1, b1, w2, b2, out);
}